// round 1
// baseline (speedup 1.0000x reference)
#include <cuda_runtime.h>
#include <math.h>

// Problem dims
#define T_  512
#define B_  64
#define E_  512
#define H_  1024
#define V_  256
#define G4  4096   // 4*H (gate-interleaved: col n = 4*j + g, g in {f,i,o,c~})

// ---------------- scratch (device globals; allocation-free) ----------------
__device__ float g_Wx[E_ * G4];                     //   8 MB  packed x-part of gate weights
__device__ float g_Wh[H_ * G4];                     //  16 MB  packed h-part of gate weights
__device__ float g_bias[G4];                        //  packed biases (interleaved)
__device__ float g_Xproj[(size_t)T_ * B_ * G4];     // 512 MB  x@Wx + b for all t
__device__ float g_hbuf[2][B_ * H_];                //  h double buffer
__device__ float g_c[B_ * H_];                      //  cell state
__device__ float g_hseq[(size_t)T_ * B_ * H_];      // 128 MB  all h_t for final out GEMM

// ---------------- pack weights into interleaved-gate layout ----------------
__global__ void pack_weights(const float* __restrict__ Wf, const float* __restrict__ Wi,
                             const float* __restrict__ Wo, const float* __restrict__ Wc,
                             const float* __restrict__ bf, const float* __restrict__ bi,
                             const float* __restrict__ bo, const float* __restrict__ bc)
{
    const int totalW = (E_ + H_) * H_;
    int idx = blockIdx.x * blockDim.x + threadIdx.x;
    if (idx < totalW) {
        int k = idx / H_;           // row in (E+H)
        int j = idx % H_;           // hidden unit
        float vf = Wf[idx], vi = Wi[idx], vo = Wo[idx], vc = Wc[idx];
        if (k < E_) {
            float* dst = &g_Wx[(size_t)k * G4 + j * 4];
            dst[0] = vf; dst[1] = vi; dst[2] = vo; dst[3] = vc;
        } else {
            float* dst = &g_Wh[(size_t)(k - E_) * G4 + j * 4];
            dst[0] = vf; dst[1] = vi; dst[2] = vo; dst[3] = vc;
        }
    } else if (idx < totalW + H_) {
        int j = idx - totalW;
        g_bias[j * 4 + 0] = bf[j];
        g_bias[j * 4 + 1] = bi[j];
        g_bias[j * 4 + 2] = bo[j];
        g_bias[j * 4 + 3] = bc[j];
    }
}

// ---------------- init h / c state ----------------
__global__ void init_state(const float* __restrict__ hidden, const float* __restrict__ cell)
{
    int i = blockIdx.x * blockDim.x + threadIdx.x;
    if (i < B_ * H_) {
        g_hbuf[0][i] = hidden[i];
        g_c[i]       = cell[i];
    }
}

// ---------------- generic fp32 SGEMM with bias: C[M,N] = A[M,K] @ B[K,N] + bias[N]
// BM=BN=128, BK=8, TM=TN=8, 256 threads. M%128==0, N%128==0, K%8==0 required.
__global__ __launch_bounds__(256) void sgemm_bias(
    const float* __restrict__ A, const float* __restrict__ B,
    const float* __restrict__ bias, float* __restrict__ C,
    int M, int N, int K)
{
    __shared__ float As[8][128];
    __shared__ float Bs[8][128];
    const int tid  = threadIdx.x;
    const int cRow = blockIdx.y;
    const int cCol = blockIdx.x;

    const int innerRowA = tid >> 1;    // 0..127
    const int innerColA = tid & 1;     // float4 slot in BK=8
    const int innerRowB = tid >> 5;    // 0..7
    const int innerColB = tid & 31;    // float4 slot in BN=128
    const int threadRow = tid >> 4;    // 0..15
    const int threadCol = tid & 15;    // 0..15

    const float* Ab = A + (size_t)cRow * 128 * K;
    const float* Bb = B + (size_t)cCol * 128;

    float acc[8][8];
    #pragma unroll
    for (int i = 0; i < 8; i++)
        #pragma unroll
        for (int j = 0; j < 8; j++) acc[i][j] = 0.f;

    for (int k0 = 0; k0 < K; k0 += 8) {
        float4 a = *(const float4*)&Ab[(size_t)innerRowA * K + k0 + innerColA * 4];
        *(float4*)&Bs[innerRowB][innerColB * 4] =
            *(const float4*)&Bb[(size_t)(k0 + innerRowB) * N + innerColB * 4];
        As[innerColA * 4 + 0][innerRowA] = a.x;
        As[innerColA * 4 + 1][innerRowA] = a.y;
        As[innerColA * 4 + 2][innerRowA] = a.z;
        As[innerColA * 4 + 3][innerRowA] = a.w;
        __syncthreads();

        #pragma unroll
        for (int kk = 0; kk < 8; kk++) {
            float ar[8], br[8];
            #pragma unroll
            for (int i = 0; i < 8; i += 4)
                *(float4*)&ar[i] = *(const float4*)&As[kk][threadRow * 8 + i];
            #pragma unroll
            for (int j = 0; j < 8; j += 4)
                *(float4*)&br[j] = *(const float4*)&Bs[kk][threadCol * 8 + j];
            #pragma unroll
            for (int i = 0; i < 8; i++)
                #pragma unroll
                for (int j = 0; j < 8; j++)
                    acc[i][j] += ar[i] * br[j];
        }
        __syncthreads();
    }

    float* Cb = C + (size_t)(cRow * 128 + threadRow * 8) * N + cCol * 128 + threadCol * 8;
    const float* biasb = bias + cCol * 128 + threadCol * 8;
    #pragma unroll
    for (int i = 0; i < 8; i++) {
        #pragma unroll
        for (int j = 0; j < 8; j += 4) {
            float4 v;
            v.x = acc[i][j + 0] + biasb[j + 0];
            v.y = acc[i][j + 1] + biasb[j + 1];
            v.z = acc[i][j + 2] + biasb[j + 2];
            v.w = acc[i][j + 3] + biasb[j + 3];
            *(float4*)&Cb[(size_t)i * N + j] = v;
        }
    }
}

// ---------------- one LSTM recurrence step (fused GEMM + gate pointwise) ----
// gates[64,4096] = Xproj[t] + h_in[64,1024] @ g_Wh[1024,4096]   (gate-interleaved N)
// 128 CTAs, each: M=64 (all rows) x N-tile 32 (8 hidden units * 4 gates), K=1024.
// 128 threads: thread (trow,tcol) owns rows trow*4..+3, gate quad tcol -> computes
// f,i,o,c~ for 4 (b,j) pairs and fuses the c/h update.
__global__ __launch_bounds__(128) void lstm_step(
    const float* __restrict__ h_in, float* __restrict__ h_out,
    float* __restrict__ hseq_t, const float* __restrict__ xp_t)
{
    __shared__ float As[8][64];   // [kk][row]
    __shared__ float Bs[8][32];   // [kk][n within tile]
    const int tid  = threadIdx.x;      // 128
    const int n0   = blockIdx.x * 32;
    const int trow = tid >> 3;         // 0..15 -> rows trow*4..+3
    const int tcol = tid & 7;          // 0..7  -> cols tcol*4..+3 (one gate quad)

    float acc[4][4];
    #pragma unroll
    for (int i = 0; i < 4; i++)
        #pragma unroll
        for (int j = 0; j < 4; j++) acc[i][j] = 0.f;

    const int arow = tid >> 1;   // 0..63
    const int akq  = tid & 1;    // which float4 in BK=8

    for (int k0 = 0; k0 < H_; k0 += 8) {
        float4 av = *(const float4*)&h_in[(size_t)arow * H_ + k0 + akq * 4];
        if (tid < 64) {
            int kk = tid >> 3, nq = tid & 7;
            *(float4*)&Bs[kk][nq * 4] =
                *(const float4*)&g_Wh[(size_t)(k0 + kk) * G4 + n0 + nq * 4];
        }
        As[akq * 4 + 0][arow] = av.x;
        As[akq * 4 + 1][arow] = av.y;
        As[akq * 4 + 2][arow] = av.z;
        As[akq * 4 + 3][arow] = av.w;
        __syncthreads();

        #pragma unroll
        for (int kk = 0; kk < 8; kk++) {
            float4 a4 = *(const float4*)&As[kk][trow * 4];
            float4 b4 = *(const float4*)&Bs[kk][tcol * 4];
            float ar[4] = {a4.x, a4.y, a4.z, a4.w};
            float br[4] = {b4.x, b4.y, b4.z, b4.w};
            #pragma unroll
            for (int i = 0; i < 4; i++)
                #pragma unroll
                for (int j = 0; j < 4; j++)
                    acc[i][j] += ar[i] * br[j];
        }
        __syncthreads();
    }

    // fused LSTM gate epilogue
    const int n = n0 + tcol * 4;
    const int j = n >> 2;                 // hidden unit index
    #pragma unroll
    for (int i = 0; i < 4; i++) {
        const int b = trow * 4 + i;
        float4 x = *(const float4*)&xp_t[(size_t)b * G4 + n];
        float pf = acc[i][0] + x.x;
        float pi = acc[i][1] + x.y;
        float po = acc[i][2] + x.z;
        float pc = acc[i][3] + x.w;
        float fg = 1.f / (1.f + expf(-pf));
        float ig = 1.f / (1.f + expf(-pi));
        float og = 1.f / (1.f + expf(-po));
        float ct = tanhf(pc);
        float cold = g_c[b * H_ + j];
        float cnew = fg * cold + ig * ct;
        float hnew = og * tanhf(cnew);
        g_c[b * H_ + j]     = cnew;
        h_out[b * H_ + j]   = hnew;
        hseq_t[b * H_ + j]  = hnew;
    }
}

// ---------------- final h / c copy into output tail ----------------
__global__ void write_hc(float* __restrict__ dst)
{
    int i = blockIdx.x * blockDim.x + threadIdx.x;
    if (i < B_ * H_) {
        dst[i]            = g_hbuf[0][i];   // T_=512 even -> final h in buffer 0
        dst[B_ * H_ + i]  = g_c[i];
    }
}

// ---------------- launch ----------------
extern "C" void kernel_launch(void* const* d_in, const int* in_sizes, int n_in,
                              void* d_out, int out_size)
{
    const float* input_seq = (const float*)d_in[0];   // [T,B,E]
    const float* hidden    = (const float*)d_in[1];   // [B,H]
    const float* cell      = (const float*)d_in[2];   // [B,H]
    const float* Wf        = (const float*)d_in[3];
    const float* bf        = (const float*)d_in[4];
    const float* Wi        = (const float*)d_in[5];
    const float* bi        = (const float*)d_in[6];
    const float* Wo        = (const float*)d_in[7];
    const float* bo        = (const float*)d_in[8];
    const float* Wc        = (const float*)d_in[9];
    const float* bc        = (const float*)d_in[10];
    const float* Wout      = (const float*)d_in[11];  // [H,V]
    const float* bout      = (const float*)d_in[12];  // [V]
    float* out = (float*)d_out;  // [T*B*V] out_seq, then [B*H] h, then [B*H] c

    float *pWx, *pBias, *pX, *pHb, *pHs;
    cudaGetSymbolAddress((void**)&pWx,   g_Wx);
    cudaGetSymbolAddress((void**)&pBias, g_bias);
    cudaGetSymbolAddress((void**)&pX,    g_Xproj);
    cudaGetSymbolAddress((void**)&pHb,   g_hbuf);
    cudaGetSymbolAddress((void**)&pHs,   g_hseq);
    float* h0 = pHb;               // g_hbuf[0]
    float* h1 = pHb + B_ * H_;     // g_hbuf[1]

    // 1. pack weights (interleaved-gate layout)
    {
        int total = (E_ + H_) * H_ + H_;
        pack_weights<<<(total + 255) / 256, 256>>>(Wf, Wi, Wo, Wc, bf, bi, bo, bc);
    }

    // 2. init state
    init_state<<<(B_ * H_ + 255) / 256, 256>>>(hidden, cell);

    // 3. Xproj = input_seq @ Wx + bias   (M=32768, N=4096, K=512)
    {
        dim3 grid(G4 / 128, (T_ * B_) / 128);
        sgemm_bias<<<grid, 256>>>(input_seq, pWx, pBias, pX, T_ * B_, G4, E_);
    }

    // 4. sequential recurrence (512 steps; h double-buffered)
    for (int t = 0; t < T_; t++) {
        const float* hin  = (t & 1) ? h1 : h0;
        float*       hout = (t & 1) ? h0 : h1;
        lstm_step<<<G4 / 32, 128>>>(hin, hout,
                                    pHs + (size_t)t * B_ * H_,
                                    pX  + (size_t)t * B_ * G4);
    }

    // 5. out_seq = h_seq @ Wout + bout   (M=32768, N=256, K=1024)
    {
        dim3 grid(V_ / 128, (T_ * B_) / 128);
        sgemm_bias<<<grid, 256>>>(pHs, Wout, bout, out, T_ * B_, V_, H_);
    }

    // 6. final h, c
    write_hc<<<(B_ * H_ + 255) / 256, 256>>>(out + (size_t)T_ * B_ * V_);
}

// round 2
// speedup vs baseline: 2.0733x; 2.0733x over previous
#include <cuda_runtime.h>
#include <math.h>

// Problem dims
#define T_  512
#define B_  64
#define E_  512
#define H_  1024
#define V_  256
#define G4  4096   // 4*H (gate-interleaved: col n = 4*j + g, g in {f,i,o,c~})

#define NCTA_STEP 128   // persistent recurrence grid (<= 148 SMs -> all co-resident)

// ---------------- scratch (device globals; allocation-free) ----------------
__device__ float g_Wx[E_ * G4];                     //   8 MB  packed x-part of gate weights
__device__ float g_Wh[H_ * G4];                     //  16 MB  packed h-part of gate weights
__device__ float g_bias[G4];                        //  packed biases (interleaved)
__device__ float g_Xproj[(size_t)T_ * B_ * G4];     // 512 MB  x@Wx + b for all t
__device__ float g_hT[2][H_ * B_];                  //  transposed h double buffer: h_T[k][b]
__device__ float g_c[B_ * H_];                      //  cell state (row-major [b][j])
__device__ float g_hseq[(size_t)T_ * B_ * H_];      // 128 MB  all h_t (row-major) for out GEMM
__device__ unsigned g_bar_count;
__device__ unsigned g_bar_gen;

// ---------------- pack weights into interleaved-gate layout ----------------
__global__ void pack_weights(const float* __restrict__ Wf, const float* __restrict__ Wi,
                             const float* __restrict__ Wo, const float* __restrict__ Wc,
                             const float* __restrict__ bf, const float* __restrict__ bi,
                             const float* __restrict__ bo, const float* __restrict__ bc)
{
    const int totalW = (E_ + H_) * H_;
    int idx = blockIdx.x * blockDim.x + threadIdx.x;
    if (idx < totalW) {
        int k = idx / H_;           // row in (E+H)
        int j = idx % H_;           // hidden unit
        float vf = Wf[idx], vi = Wi[idx], vo = Wo[idx], vc = Wc[idx];
        if (k < E_) {
            float* dst = &g_Wx[(size_t)k * G4 + j * 4];
            dst[0] = vf; dst[1] = vi; dst[2] = vo; dst[3] = vc;
        } else {
            float* dst = &g_Wh[(size_t)(k - E_) * G4 + j * 4];
            dst[0] = vf; dst[1] = vi; dst[2] = vo; dst[3] = vc;
        }
    } else if (idx < totalW + H_) {
        int j = idx - totalW;
        g_bias[j * 4 + 0] = bf[j];
        g_bias[j * 4 + 1] = bi[j];
        g_bias[j * 4 + 2] = bo[j];
        g_bias[j * 4 + 3] = bc[j];
    }
}

// ---------------- init state: transpose h0 into g_hT[0], copy c, reset barrier ----
__global__ void init_state(const float* __restrict__ hidden, const float* __restrict__ cell)
{
    int i = blockIdx.x * blockDim.x + threadIdx.x;
    if (i < B_ * H_) {
        int b = i / H_, k = i % H_;
        g_hT[0][k * B_ + b] = hidden[i];
        g_c[i]              = cell[i];
    }
    if (i == 0) { g_bar_count = 0; g_bar_gen = 0; }
}

// ---------------- generic fp32 SGEMM with bias: C[M,N] = A[M,K] @ B[K,N] + bias[N]
// BM=BN=128, BK=8, TM=TN=8, 256 threads. M%128==0, N%128==0, K%8==0 required.
__global__ __launch_bounds__(256) void sgemm_bias(
    const float* __restrict__ A, const float* __restrict__ B,
    const float* __restrict__ bias, float* __restrict__ C,
    int M, int N, int K)
{
    __shared__ float As[8][128];
    __shared__ float Bs[8][128];
    const int tid  = threadIdx.x;
    const int cRow = blockIdx.y;
    const int cCol = blockIdx.x;

    const int innerRowA = tid >> 1;
    const int innerColA = tid & 1;
    const int innerRowB = tid >> 5;
    const int innerColB = tid & 31;
    const int threadRow = tid >> 4;
    const int threadCol = tid & 15;

    const float* Ab = A + (size_t)cRow * 128 * K;
    const float* Bb = B + (size_t)cCol * 128;

    float acc[8][8];
    #pragma unroll
    for (int i = 0; i < 8; i++)
        #pragma unroll
        for (int j = 0; j < 8; j++) acc[i][j] = 0.f;

    for (int k0 = 0; k0 < K; k0 += 8) {
        float4 a = *(const float4*)&Ab[(size_t)innerRowA * K + k0 + innerColA * 4];
        *(float4*)&Bs[innerRowB][innerColB * 4] =
            *(const float4*)&Bb[(size_t)(k0 + innerRowB) * N + innerColB * 4];
        As[innerColA * 4 + 0][innerRowA] = a.x;
        As[innerColA * 4 + 1][innerRowA] = a.y;
        As[innerColA * 4 + 2][innerRowA] = a.z;
        As[innerColA * 4 + 3][innerRowA] = a.w;
        __syncthreads();

        #pragma unroll
        for (int kk = 0; kk < 8; kk++) {
            float ar[8], br[8];
            #pragma unroll
            for (int i = 0; i < 8; i += 4)
                *(float4*)&ar[i] = *(const float4*)&As[kk][threadRow * 8 + i];
            #pragma unroll
            for (int j = 0; j < 8; j += 4)
                *(float4*)&br[j] = *(const float4*)&Bs[kk][threadCol * 8 + j];
            #pragma unroll
            for (int i = 0; i < 8; i++)
                #pragma unroll
                for (int j = 0; j < 8; j++)
                    acc[i][j] += ar[i] * br[j];
        }
        __syncthreads();
    }

    float* Cb = C + (size_t)(cRow * 128 + threadRow * 8) * N + cCol * 128 + threadCol * 8;
    const float* biasb = bias + cCol * 128 + threadCol * 8;
    #pragma unroll
    for (int i = 0; i < 8; i++) {
        #pragma unroll
        for (int j = 0; j < 8; j += 4) {
            float4 v;
            v.x = acc[i][j + 0] + biasb[j + 0];
            v.y = acc[i][j + 1] + biasb[j + 1];
            v.z = acc[i][j + 2] + biasb[j + 2];
            v.w = acc[i][j + 3] + biasb[j + 3];
            *(float4*)&Cb[(size_t)i * N + j] = v;
        }
    }
}

// ---------------- persistent LSTM recurrence ----------------
// 128 CTAs x 128 threads. CTA owns 32 gate-columns (8 hidden units). All 512
// steps in one kernel with a device-wide barrier per step. h kept transposed
// (h_T[k][b]) so smem A copies are direct & conflict-free.
__global__ __launch_bounds__(128, 1) void lstm_persistent()
{
    __shared__ float As[2][32][64];   // [buf][kk][b]
    __shared__ float Bs[2][32][32];   // [buf][kk][col]

    const int tid  = threadIdx.x;
    const int n0   = blockIdx.x * 32;
    const int trow = tid >> 3;        // 0..15 -> rows (b) trow*4..+3
    const int tcol = tid & 7;         // 0..7  -> gate quad (cols tcol*4..+3)
    const int jh   = (n0 >> 2) + tcol;   // hidden unit index this thread owns

    for (int t = 0; t < T_; t++) {
        const float* hT_in  = g_hT[t & 1];
        float*       hT_out = g_hT[(t + 1) & 1];
        const float* xp_t   = g_Xproj + (size_t)t * B_ * G4;
        float*       hs_t   = g_hseq  + (size_t)t * B_ * H_;

        // prefetch per-step epilogue operands (land during the 17us GEMM)
        float4 xpv[4];
        float  cv[4];
        #pragma unroll
        for (int i = 0; i < 4; i++) {
            int b = trow * 4 + i;
            xpv[i] = *(const float4*)&xp_t[(size_t)b * G4 + n0 + tcol * 4];
            cv[i]  = g_c[b * H_ + jh];
        }

        float acc[4][4];
        #pragma unroll
        for (int i = 0; i < 4; i++)
            #pragma unroll
            for (int j = 0; j < 4; j++) acc[i][j] = 0.f;

        // ---- K loop: BK=32, double-buffered smem, reg-staged global loads ----
        float4 a_st[4], b_st[2];
        // block 0 load + store
        {
            #pragma unroll
            for (int q = 0; q < 4; q++) {
                int lin = tid + q * 128;          // 0..511 float4s
                int kk = lin >> 4, b4 = lin & 15;
                a_st[q] = *(const float4*)&hT_in[kk * B_ + b4 * 4];
            }
            #pragma unroll
            for (int q = 0; q < 2; q++) {
                int lin = tid + q * 128;          // 0..255 float4s
                int kk = lin >> 3, c4 = lin & 7;
                b_st[q] = *(const float4*)&g_Wh[(size_t)kk * G4 + n0 + c4 * 4];
            }
            #pragma unroll
            for (int q = 0; q < 4; q++) {
                int lin = tid + q * 128;
                int kk = lin >> 4, b4 = lin & 15;
                *(float4*)&As[0][kk][b4 * 4] = a_st[q];
            }
            #pragma unroll
            for (int q = 0; q < 2; q++) {
                int lin = tid + q * 128;
                int kk = lin >> 3, c4 = lin & 7;
                *(float4*)&Bs[0][kk][c4 * 4] = b_st[q];
            }
        }

        #pragma unroll 1
        for (int blk = 0; blk < H_ / 32; blk++) {
            const int buf = blk & 1;
            __syncthreads();   // current buf filled; other buf free

            const int k0n = (blk + 1) * 32;
            if (k0n < H_) {
                #pragma unroll
                for (int q = 0; q < 4; q++) {
                    int lin = tid + q * 128;
                    int kk = lin >> 4, b4 = lin & 15;
                    a_st[q] = *(const float4*)&hT_in[(k0n + kk) * B_ + b4 * 4];
                }
                #pragma unroll
                for (int q = 0; q < 2; q++) {
                    int lin = tid + q * 128;
                    int kk = lin >> 3, c4 = lin & 7;
                    b_st[q] = *(const float4*)&g_Wh[(size_t)(k0n + kk) * G4 + n0 + c4 * 4];
                }
            }

            #pragma unroll
            for (int kk = 0; kk < 32; kk++) {
                float4 a4 = *(const float4*)&As[buf][kk][trow * 4];
                float4 b4 = *(const float4*)&Bs[buf][kk][tcol * 4];
                float ar[4] = {a4.x, a4.y, a4.z, a4.w};
                float br[4] = {b4.x, b4.y, b4.z, b4.w};
                #pragma unroll
                for (int i = 0; i < 4; i++)
                    #pragma unroll
                    for (int j = 0; j < 4; j++)
                        acc[i][j] += ar[i] * br[j];
            }

            if (k0n < H_) {
                const int nb = buf ^ 1;
                #pragma unroll
                for (int q = 0; q < 4; q++) {
                    int lin = tid + q * 128;
                    int kk = lin >> 4, b4 = lin & 15;
                    *(float4*)&As[nb][kk][b4 * 4] = a_st[q];
                }
                #pragma unroll
                for (int q = 0; q < 2; q++) {
                    int lin = tid + q * 128;
                    int kk = lin >> 3, c4 = lin & 7;
                    *(float4*)&Bs[nb][kk][c4 * 4] = b_st[q];
                }
            }
        }

        // ---- fused LSTM gate epilogue ----
        #pragma unroll
        for (int i = 0; i < 4; i++) {
            const int b = trow * 4 + i;
            float pf = acc[i][0] + xpv[i].x;
            float pi = acc[i][1] + xpv[i].y;
            float po = acc[i][2] + xpv[i].z;
            float pc = acc[i][3] + xpv[i].w;
            float fg = 1.f / (1.f + expf(-pf));
            float ig = 1.f / (1.f + expf(-pi));
            float og = 1.f / (1.f + expf(-po));
            float ct = tanhf(pc);
            float cnew = fg * cv[i] + ig * ct;
            float hnew = og * tanhf(cnew);
            g_c[b * H_ + jh]      = cnew;
            hT_out[jh * B_ + b]   = hnew;   // transposed for next step's A copy
            hs_t[b * H_ + jh]     = hnew;   // row-major for out GEMM
        }

        // ---- device-wide barrier: release step t ----
        __syncthreads();
        if (tid == 0) {
            __threadfence();
            unsigned old = atomicAdd(&g_bar_count, 1);
            if (old == (unsigned)(gridDim.x - 1)) {
                g_bar_count = 0;
                __threadfence();
                atomicExch(&g_bar_gen, (unsigned)(t + 1));
            } else {
                while (atomicAdd(&g_bar_gen, 0u) < (unsigned)(t + 1)) { }
            }
            __threadfence();
        }
        __syncthreads();
    }
}

// ---------------- final h / c copy into output tail ----------------
__global__ void write_hc(float* __restrict__ dst)
{
    int i = blockIdx.x * blockDim.x + threadIdx.x;
    if (i < B_ * H_) {
        dst[i]           = g_hseq[(size_t)(T_ - 1) * B_ * H_ + i];
        dst[B_ * H_ + i] = g_c[i];
    }
}

// ---------------- launch ----------------
extern "C" void kernel_launch(void* const* d_in, const int* in_sizes, int n_in,
                              void* d_out, int out_size)
{
    const float* input_seq = (const float*)d_in[0];   // [T,B,E]
    const float* hidden    = (const float*)d_in[1];   // [B,H]
    const float* cell      = (const float*)d_in[2];   // [B,H]
    const float* Wf        = (const float*)d_in[3];
    const float* bf        = (const float*)d_in[4];
    const float* Wi        = (const float*)d_in[5];
    const float* bi        = (const float*)d_in[6];
    const float* Wo        = (const float*)d_in[7];
    const float* bo        = (const float*)d_in[8];
    const float* Wc        = (const float*)d_in[9];
    const float* bc        = (const float*)d_in[10];
    const float* Wout      = (const float*)d_in[11];  // [H,V]
    const float* bout      = (const float*)d_in[12];  // [V]
    float* out = (float*)d_out;  // [T*B*V] out_seq, then [B,H] h, then [B,H] c

    float *pWx, *pBias, *pX, *pHs;
    cudaGetSymbolAddress((void**)&pWx,   g_Wx);
    cudaGetSymbolAddress((void**)&pBias, g_bias);
    cudaGetSymbolAddress((void**)&pX,    g_Xproj);
    cudaGetSymbolAddress((void**)&pHs,   g_hseq);

    // 1. pack weights (interleaved-gate layout)
    {
        int total = (E_ + H_) * H_ + H_;
        pack_weights<<<(total + 255) / 256, 256>>>(Wf, Wi, Wo, Wc, bf, bi, bo, bc);
    }

    // 2. init state (transposed h) + barrier reset
    init_state<<<(B_ * H_ + 255) / 256, 256>>>(hidden, cell);

    // 3. Xproj = input_seq @ Wx + bias   (M=32768, N=4096, K=512)
    {
        dim3 grid(G4 / 128, (T_ * B_) / 128);
        sgemm_bias<<<grid, 256>>>(input_seq, pWx, pBias, pX, T_ * B_, G4, E_);
    }

    // 4. whole recurrence in ONE persistent kernel
    lstm_persistent<<<NCTA_STEP, 128>>>();

    // 5. out_seq = h_seq @ Wout + bout   (M=32768, N=256, K=1024)
    {
        dim3 grid(V_ / 128, (T_ * B_) / 128);
        sgemm_bias<<<grid, 256>>>(pHs, Wout, bout, out, T_ * B_, V_, H_);
    }

    // 6. final h, c
    write_hc<<<(B_ * H_ + 255) / 256, 256>>>(out + (size_t)T_ * B_ * V_);
}

// round 6
// speedup vs baseline: 2.3841x; 1.1499x over previous
#include <cuda_runtime.h>
#include <cuda_bf16.h>
#include <math.h>
#include <stdint.h>

// Problem dims
#define T_  512
#define B_  64
#define E_  512
#define H_  1024
#define V_  256
#define G4  4096   // 4*H gate-interleaved: col n = 4*j + g

#define NCTA_STEP 128

// ---------------- scratch (device globals; allocation-free) ----------------
__device__ float g_Wh[H_ * G4];                       // fp32 recurrent weights (interleaved)
__device__ float g_bias[G4];                          // packed gate biases
__device__ float g_Xproj[(size_t)T_ * B_ * G4];       // 512 MB
__device__ float g_hT[2][H_ * B_];
__device__ float g_c[B_ * H_];
__device__ float g_hseq[(size_t)T_ * B_ * H_];        // 128 MB
__device__ unsigned g_bar_count;
__device__ unsigned g_bar_gen;

// bf16 split operands (16B aligned for vector/cp.async tile copies)
__device__ __align__(16) __nv_bfloat16 g_Ahi[(size_t)T_ * B_ * E_];   // input_seq hi
__device__ __align__(16) __nv_bfloat16 g_Alo[(size_t)T_ * B_ * E_];
__device__ __align__(16) __nv_bfloat16 g_WxThi[G4 * E_];              // WxT[n][k]
__device__ __align__(16) __nv_bfloat16 g_WxTlo[G4 * E_];
__device__ __align__(16) __nv_bfloat16 g_WoThi[V_ * H_];              // WoutT[v][k]
__device__ __align__(16) __nv_bfloat16 g_WoTlo[V_ * H_];
__device__ __align__(16) __nv_bfloat16 g_Hshi[(size_t)T_ * B_ * H_];
__device__ __align__(16) __nv_bfloat16 g_Hslo[(size_t)T_ * B_ * H_];

// ---------------- PTX helpers (all plain-sm_100 legal: sm_80-era MMA path) ----------------
__device__ __forceinline__ uint32_t smem_u32(const void* p) {
    uint32_t a;
    asm("{ .reg .u64 t; cvta.to.shared.u64 t, %1; cvt.u32.u64 %0, t; }" : "=r"(a) : "l"(p));
    return a;
}
#define SWZ128(o) ((o) ^ (((o) >> 3) & 0x70))

#define CP16(dst, src) \
    asm volatile("cp.async.cg.shared.global [%0], [%1], 16;" :: "r"(dst), "l"(src))
#define CP_COMMIT() asm volatile("cp.async.commit_group;" ::: "memory")
#define CP_WAIT1()  asm volatile("cp.async.wait_group 1;" ::: "memory")
#define CP_WAIT0()  asm volatile("cp.async.wait_group 0;" ::: "memory")

#define LDSM4(r, addr) \
    asm volatile("ldmatrix.sync.aligned.m8n8.x4.shared.b16 {%0,%1,%2,%3}, [%4];" \
        : "=r"((r)[0]), "=r"((r)[1]), "=r"((r)[2]), "=r"((r)[3]) : "r"(addr))

#define MMA16816(c, a, b0, b1) \
    asm volatile("mma.sync.aligned.m16n8k16.row.col.f32.bf16.bf16.f32 " \
        "{%0,%1,%2,%3}, {%4,%5,%6,%7}, {%8,%9}, {%0,%1,%2,%3};" \
        : "+f"((c)[0]), "+f"((c)[1]), "+f"((c)[2]), "+f"((c)[3]) \
        : "r"((a)[0]), "r"((a)[1]), "r"((a)[2]), "r"((a)[3]), "r"(b0), "r"(b1))

__device__ __forceinline__ void split_bf16(float v, __nv_bfloat16& hi, __nv_bfloat16& lo) {
    hi = __float2bfloat16(v);
    lo = __float2bfloat16(v - __bfloat162float(hi));
}

// ---------------- pack: Wh fp32 interleaved, WxT bf16 splits, bias ----------------
__global__ void pack_gates(const float* __restrict__ Wf, const float* __restrict__ Wi,
                           const float* __restrict__ Wo, const float* __restrict__ Wc,
                           const float* __restrict__ bf, const float* __restrict__ bi,
                           const float* __restrict__ bo, const float* __restrict__ bc)
{
    const int totalW = (E_ + H_) * H_;
    int idx = blockIdx.x * blockDim.x + threadIdx.x;
    if (idx < totalW) {
        int k = idx / H_;
        int j = idx % H_;
        float v[4] = {Wf[idx], Wi[idx], Wo[idx], Wc[idx]};
        if (k < E_) {
            #pragma unroll
            for (int g = 0; g < 4; g++) {
                __nv_bfloat16 hi, lo;
                split_bf16(v[g], hi, lo);
                size_t o = (size_t)(j * 4 + g) * E_ + k;
                g_WxThi[o] = hi;
                g_WxTlo[o] = lo;
            }
        } else {
            float* dst = &g_Wh[(size_t)(k - E_) * G4 + j * 4];
            dst[0] = v[0]; dst[1] = v[1]; dst[2] = v[2]; dst[3] = v[3];
        }
    } else if (idx < totalW + H_) {
        int j = idx - totalW;
        g_bias[j * 4 + 0] = bf[j];
        g_bias[j * 4 + 1] = bi[j];
        g_bias[j * 4 + 2] = bo[j];
        g_bias[j * 4 + 3] = bc[j];
    }
}

__global__ void pack_wout(const float* __restrict__ Wout)
{
    int idx = blockIdx.x * blockDim.x + threadIdx.x;   // over V_*H_
    if (idx < V_ * H_) {
        int v = idx % V_, k = idx / V_;   // Wout[k*V + v]
        __nv_bfloat16 hi, lo;
        split_bf16(Wout[idx], hi, lo);
        size_t o = (size_t)v * H_ + k;
        g_WoThi[o] = hi;
        g_WoTlo[o] = lo;
    }
}

__global__ void split_src(const float* __restrict__ src, __nv_bfloat16* __restrict__ hi,
                          __nv_bfloat16* __restrict__ lo, size_t n)
{
    size_t i = (size_t)blockIdx.x * blockDim.x + threadIdx.x;
    if (i < n) {
        __nv_bfloat16 h, l;
        split_bf16(src[i], h, l);
        hi[i] = h;
        lo[i] = l;
    }
}

// ---------------- init state ----------------
__global__ void init_state(const float* __restrict__ hidden, const float* __restrict__ cell)
{
    int i = blockIdx.x * blockDim.x + threadIdx.x;
    if (i < B_ * H_) {
        int b = i / H_, k = i % H_;
        g_hT[0][k * B_ + b] = hidden[i];
        g_c[i]              = cell[i];
    }
    if (i == 0) { g_bar_count = 0; g_bar_gen = 0; }
}

// ---------------- bf16x3 split GEMM on mma.sync tensor cores ----------------
// C[M,N] = Ahi@Bhi^T + Ahi@Blo^T + Alo@Bhi^T + bias
// A: M x K rows K-contig; B: N x K rows K-contig; fp32 accum.
// CTA tile 128x128, K-chunk 64. 8 warps = 4(m) x 2(n); warp tile 32x64.
// cp.async double-buffered stages, SW128 swizzle, ldmatrix fragment loads.
#define STG_BYTES   65536
#define OFF_AHI     0
#define OFF_ALO     16384
#define OFF_BHI     32768
#define OFF_BLO     49152
#define GEMM_SMEM   (2 * STG_BYTES)

__device__ __forceinline__ void stage_fill(
    uint32_t sstage,
    const __nv_bfloat16* __restrict__ Ahi, const __nv_bfloat16* __restrict__ Alo,
    const __nv_bfloat16* __restrict__ Bhi, const __nv_bfloat16* __restrict__ Blo,
    int m0, int n0, int kc, int K, int tid)
{
    #pragma unroll
    for (int i = 0; i < 4; i++) {
        int u  = tid + i * 256;        // 0..1023
        int r  = u >> 3;
        int cu = u & 7;
        uint32_t dsw = SWZ128((uint32_t)(r * 128 + cu * 16));
        size_t ao = (size_t)(m0 + r) * K + kc + cu * 8;
        size_t bo = (size_t)(n0 + r) * K + kc + cu * 8;
        CP16(sstage + OFF_AHI + dsw, Ahi + ao);
        CP16(sstage + OFF_ALO + dsw, Alo + ao);
        CP16(sstage + OFF_BHI + dsw, Bhi + bo);
        CP16(sstage + OFF_BLO + dsw, Blo + bo);
    }
}

__global__ __launch_bounds__(256, 1) void gemm_bf16x3(
    const __nv_bfloat16* __restrict__ Ahi, const __nv_bfloat16* __restrict__ Alo,
    const __nv_bfloat16* __restrict__ Bhi, const __nv_bfloat16* __restrict__ Blo,
    const float* __restrict__ bias, float* __restrict__ C,
    int K, int ldc)
{
    extern __shared__ char smem[];
    const uint32_t sbase = smem_u32(smem);
    const int tid  = threadIdx.x;
    const int lane = tid & 31;
    const int w    = tid >> 5;
    const int wm   = w & 3;         // m offset wm*32
    const int wn   = w >> 2;        // n offset wn*64
    const int m0 = blockIdx.y * 128;
    const int n0 = blockIdx.x * 128;
    const int NC = K / 64;

    float acc[2][8][4];
    #pragma unroll
    for (int mt = 0; mt < 2; mt++)
        #pragma unroll
        for (int nt = 0; nt < 8; nt++)
            #pragma unroll
            for (int q = 0; q < 4; q++) acc[mt][nt][q] = 0.f;

    stage_fill(sbase, Ahi, Alo, Bhi, Blo, m0, n0, 0, K, tid);
    CP_COMMIT();

    // ldmatrix lane addressing (canonical x4 pattern)
    const int a_row = (lane & 15);
    const int a_cuh = (lane >> 4);                        // 0/1: 16-byte half of k16
    const int b_row = (lane & 7) + ((lane >> 4) << 3);    // n-rows of two n8 tiles
    const int b_cuh = ((lane >> 3) & 1);

    #pragma unroll 1
    for (int c = 0; c < NC; c++) {
        if (c + 1 < NC) {
            stage_fill(sbase + ((c + 1) & 1) * STG_BYTES, Ahi, Alo, Bhi, Blo,
                       m0, n0, (c + 1) * 64, K, tid);
            CP_COMMIT();
            CP_WAIT1();
        } else {
            CP_WAIT0();
        }
        __syncthreads();

        const uint32_t sS = sbase + (c & 1) * STG_BYTES;

        #pragma unroll
        for (int ks = 0; ks < 4; ks++) {
            uint32_t aH[2][4], aL[2][4], bH[4][4], bL[4][4];
            #pragma unroll
            for (int mt = 0; mt < 2; mt++) {
                int row = wm * 32 + mt * 16 + a_row;
                int cu  = ks * 2 + a_cuh;
                uint32_t off = SWZ128((uint32_t)(row * 128 + cu * 16));
                LDSM4(aH[mt], sS + OFF_AHI + off);
                LDSM4(aL[mt], sS + OFF_ALO + off);
            }
            #pragma unroll
            for (int np = 0; np < 4; np++) {
                int row = wn * 64 + np * 16 + b_row;
                int cu  = ks * 2 + b_cuh;
                uint32_t off = SWZ128((uint32_t)(row * 128 + cu * 16));
                LDSM4(bH[np], sS + OFF_BHI + off);
                LDSM4(bL[np], sS + OFF_BLO + off);
            }
            #pragma unroll
            for (int mt = 0; mt < 2; mt++)
                #pragma unroll
                for (int np = 0; np < 4; np++) {
                    MMA16816(acc[mt][2 * np],     aH[mt], bH[np][0], bH[np][1]);
                    MMA16816(acc[mt][2 * np + 1], aH[mt], bH[np][2], bH[np][3]);
                    MMA16816(acc[mt][2 * np],     aL[mt], bH[np][0], bH[np][1]);
                    MMA16816(acc[mt][2 * np + 1], aL[mt], bH[np][2], bH[np][3]);
                    MMA16816(acc[mt][2 * np],     aH[mt], bL[np][0], bL[np][1]);
                    MMA16816(acc[mt][2 * np + 1], aH[mt], bL[np][2], bL[np][3]);
                }
        }
        __syncthreads();   // compute done before this buffer is refilled
    }

    // epilogue: mma C-frag layout -> gmem + bias
    #pragma unroll
    for (int mt = 0; mt < 2; mt++) {
        int rbase = m0 + wm * 32 + mt * 16 + (lane >> 2);
        #pragma unroll
        for (int nt = 0; nt < 8; nt++) {
            int col = n0 + wn * 64 + nt * 8 + (lane & 3) * 2;
            float2 bv = *(const float2*)&bias[col];
            float2 v0, v1;
            v0.x = acc[mt][nt][0] + bv.x;
            v0.y = acc[mt][nt][1] + bv.y;
            v1.x = acc[mt][nt][2] + bv.x;
            v1.y = acc[mt][nt][3] + bv.y;
            *(float2*)&C[(size_t)rbase * ldc + col]       = v0;
            *(float2*)&C[(size_t)(rbase + 8) * ldc + col] = v1;
        }
    }
}

// ---------------- persistent LSTM recurrence (fp32 path) ----------------
__global__ __launch_bounds__(128, 1) void lstm_persistent()
{
    __shared__ float As[2][32][64];
    __shared__ float Bs[2][32][32];

    const int tid  = threadIdx.x;
    const int n0   = blockIdx.x * 32;
    const int trow = tid >> 3;
    const int tcol = tid & 7;
    const int jh   = (n0 >> 2) + tcol;

    for (int t = 0; t < T_; t++) {
        const float* hT_in  = g_hT[t & 1];
        float*       hT_out = g_hT[(t + 1) & 1];
        const float* xp_t   = g_Xproj + (size_t)t * B_ * G4;
        float*       hs_t   = g_hseq  + (size_t)t * B_ * H_;

        float4 xpv[4];
        float  cv[4];
        #pragma unroll
        for (int i = 0; i < 4; i++) {
            int b = trow * 4 + i;
            xpv[i] = *(const float4*)&xp_t[(size_t)b * G4 + n0 + tcol * 4];
            cv[i]  = g_c[b * H_ + jh];
        }

        float acc[4][4];
        #pragma unroll
        for (int i = 0; i < 4; i++)
            #pragma unroll
            for (int j = 0; j < 4; j++) acc[i][j] = 0.f;

        float4 a_st[4], b_st[2];
        {
            #pragma unroll
            for (int q = 0; q < 4; q++) {
                int lin = tid + q * 128;
                int kk = lin >> 4, b4 = lin & 15;
                a_st[q] = *(const float4*)&hT_in[kk * B_ + b4 * 4];
            }
            #pragma unroll
            for (int q = 0; q < 2; q++) {
                int lin = tid + q * 128;
                int kk = lin >> 3, c4 = lin & 7;
                b_st[q] = *(const float4*)&g_Wh[(size_t)kk * G4 + n0 + c4 * 4];
            }
            #pragma unroll
            for (int q = 0; q < 4; q++) {
                int lin = tid + q * 128;
                int kk = lin >> 4, b4 = lin & 15;
                *(float4*)&As[0][kk][b4 * 4] = a_st[q];
            }
            #pragma unroll
            for (int q = 0; q < 2; q++) {
                int lin = tid + q * 128;
                int kk = lin >> 3, c4 = lin & 7;
                *(float4*)&Bs[0][kk][c4 * 4] = b_st[q];
            }
        }

        #pragma unroll 1
        for (int blk = 0; blk < H_ / 32; blk++) {
            const int buf = blk & 1;
            __syncthreads();

            const int k0n = (blk + 1) * 32;
            if (k0n < H_) {
                #pragma unroll
                for (int q = 0; q < 4; q++) {
                    int lin = tid + q * 128;
                    int kk = lin >> 4, b4 = lin & 15;
                    a_st[q] = *(const float4*)&hT_in[(k0n + kk) * B_ + b4 * 4];
                }
                #pragma unroll
                for (int q = 0; q < 2; q++) {
                    int lin = tid + q * 128;
                    int kk = lin >> 3, c4 = lin & 7;
                    b_st[q] = *(const float4*)&g_Wh[(size_t)(k0n + kk) * G4 + n0 + c4 * 4];
                }
            }

            #pragma unroll
            for (int kk = 0; kk < 32; kk++) {
                float4 a4 = *(const float4*)&As[buf][kk][trow * 4];
                float4 b4 = *(const float4*)&Bs[buf][kk][tcol * 4];
                float ar[4] = {a4.x, a4.y, a4.z, a4.w};
                float br[4] = {b4.x, b4.y, b4.z, b4.w};
                #pragma unroll
                for (int i = 0; i < 4; i++)
                    #pragma unroll
                    for (int j = 0; j < 4; j++)
                        acc[i][j] += ar[i] * br[j];
            }

            if (k0n < H_) {
                const int nb = buf ^ 1;
                #pragma unroll
                for (int q = 0; q < 4; q++) {
                    int lin = tid + q * 128;
                    int kk = lin >> 4, b4 = lin & 15;
                    *(float4*)&As[nb][kk][b4 * 4] = a_st[q];
                }
                #pragma unroll
                for (int q = 0; q < 2; q++) {
                    int lin = tid + q * 128;
                    int kk = lin >> 3, c4 = lin & 7;
                    *(float4*)&Bs[nb][kk][c4 * 4] = b_st[q];
                }
            }
        }

        #pragma unroll
        for (int i = 0; i < 4; i++) {
            const int b = trow * 4 + i;
            float pf = acc[i][0] + xpv[i].x;
            float pi = acc[i][1] + xpv[i].y;
            float po = acc[i][2] + xpv[i].z;
            float pc = acc[i][3] + xpv[i].w;
            float fg = 1.f / (1.f + expf(-pf));
            float ig = 1.f / (1.f + expf(-pi));
            float og = 1.f / (1.f + expf(-po));
            float ct = tanhf(pc);
            float cnew = fg * cv[i] + ig * ct;
            float hnew = og * tanhf(cnew);
            g_c[b * H_ + jh]      = cnew;
            hT_out[jh * B_ + b]   = hnew;
            hs_t[b * H_ + jh]     = hnew;
        }

        __syncthreads();
        if (tid == 0) {
            __threadfence();
            unsigned old = atomicAdd(&g_bar_count, 1);
            if (old == (unsigned)(gridDim.x - 1)) {
                g_bar_count = 0;
                __threadfence();
                atomicExch(&g_bar_gen, (unsigned)(t + 1));
            } else {
                while (atomicAdd(&g_bar_gen, 0u) < (unsigned)(t + 1)) { }
            }
            __threadfence();
        }
        __syncthreads();
    }
}

// ---------------- final h / c copy ----------------
__global__ void write_hc(float* __restrict__ dst)
{
    int i = blockIdx.x * blockDim.x + threadIdx.x;
    if (i < B_ * H_) {
        dst[i]           = g_hseq[(size_t)(T_ - 1) * B_ * H_ + i];
        dst[B_ * H_ + i] = g_c[i];
    }
}

// ---------------- launch ----------------
extern "C" void kernel_launch(void* const* d_in, const int* in_sizes, int n_in,
                              void* d_out, int out_size)
{
    const float* input_seq = (const float*)d_in[0];
    const float* hidden    = (const float*)d_in[1];
    const float* cell      = (const float*)d_in[2];
    const float* Wf        = (const float*)d_in[3];
    const float* bf        = (const float*)d_in[4];
    const float* Wi        = (const float*)d_in[5];
    const float* bi        = (const float*)d_in[6];
    const float* Wo        = (const float*)d_in[7];
    const float* bo        = (const float*)d_in[8];
    const float* Wc        = (const float*)d_in[9];
    const float* bc        = (const float*)d_in[10];
    const float* Wout      = (const float*)d_in[11];
    const float* bout      = (const float*)d_in[12];
    float* out = (float*)d_out;

    // idempotent, non-stream-ordered; called unconditionally (no static guards)
    cudaFuncSetAttribute(gemm_bf16x3, cudaFuncAttributeMaxDynamicSharedMemorySize, GEMM_SMEM);

    float *pBias, *pX, *pHs;
    __nv_bfloat16 *pAhi, *pAlo, *pWxh, *pWxl, *pWoh, *pWol, *pHsh, *pHsl;
    cudaGetSymbolAddress((void**)&pBias, g_bias);
    cudaGetSymbolAddress((void**)&pX,    g_Xproj);
    cudaGetSymbolAddress((void**)&pHs,   g_hseq);
    cudaGetSymbolAddress((void**)&pAhi,  g_Ahi);
    cudaGetSymbolAddress((void**)&pAlo,  g_Alo);
    cudaGetSymbolAddress((void**)&pWxh,  g_WxThi);
    cudaGetSymbolAddress((void**)&pWxl,  g_WxTlo);
    cudaGetSymbolAddress((void**)&pWoh,  g_WoThi);
    cudaGetSymbolAddress((void**)&pWol,  g_WoTlo);
    cudaGetSymbolAddress((void**)&pHsh,  g_Hshi);
    cudaGetSymbolAddress((void**)&pHsl,  g_Hslo);

    // 1. packs + splits
    {
        int total = (E_ + H_) * H_ + H_;
        pack_gates<<<(total + 255) / 256, 256>>>(Wf, Wi, Wo, Wc, bf, bi, bo, bc);
    }
    pack_wout<<<(V_ * H_ + 255) / 256, 256>>>(Wout);
    {
        size_t n = (size_t)T_ * B_ * E_;
        split_src<<<(int)((n + 255) / 256), 256>>>(input_seq, pAhi, pAlo, n);
    }
    init_state<<<(B_ * H_ + 255) / 256, 256>>>(hidden, cell);

    // 2. Xproj = A @ WxT^T + bias  on tensor cores (M=32768, N=4096, K=512)
    {
        dim3 grid(G4 / 128, (T_ * B_) / 128);
        gemm_bf16x3<<<grid, 256, GEMM_SMEM>>>(pAhi, pAlo, pWxh, pWxl, pBias, pX, E_, G4);
    }

    // 3. recurrence
    lstm_persistent<<<NCTA_STEP, 128>>>();

    // 4. split hseq, then out GEMM (M=32768, N=256, K=1024)
    {
        size_t n = (size_t)T_ * B_ * H_;
        split_src<<<(int)((n + 255) / 256), 256>>>(pHs, pHsh, pHsl, n);
    }
    {
        dim3 grid(V_ / 128, (T_ * B_) / 128);
        gemm_bf16x3<<<grid, 256, GEMM_SMEM>>>(pHsh, pHsl, pWoh, pWol, bout, out, H_, V_);
    }

    // 5. final h, c
    write_hc<<<(B_ * H_ + 255) / 256, 256>>>(out + (size_t)T_ * B_ * V_);
}

// round 7
// speedup vs baseline: 3.9911x; 1.6741x over previous
#include <cuda_runtime.h>
#include <cuda_bf16.h>
#include <math.h>
#include <stdint.h>

// Problem dims
#define T_  512
#define B_  64
#define E_  512
#define H_  1024
#define V_  256
#define G4  4096   // 4*H gate-interleaved: col n = 4*j + g

#define NCTA_STEP 128
#define BH  (B_ * H_)

// ---------------- scratch (device globals; allocation-free) ----------------
__device__ float g_bias[G4];                          // packed gate biases
__device__ float g_Xproj[(size_t)T_ * B_ * G4];       // 512 MB
__device__ float g_c[B_ * H_];
__device__ unsigned g_bar_count;
__device__ unsigned g_bar_gen;

// bf16 split operands (16B aligned)
__device__ __align__(16) __nv_bfloat16 g_Ahi[(size_t)T_ * B_ * E_];   // input_seq hi
__device__ __align__(16) __nv_bfloat16 g_Alo[(size_t)T_ * B_ * E_];
__device__ __align__(16) __nv_bfloat16 g_WxThi[G4 * E_];              // WxT[n][k]
__device__ __align__(16) __nv_bfloat16 g_WxTlo[G4 * E_];
__device__ __align__(16) __nv_bfloat16 g_WhThi[G4 * H_];              // WhT[n][k] recurrent
__device__ __align__(16) __nv_bfloat16 g_WhTlo[G4 * H_];
__device__ __align__(16) __nv_bfloat16 g_WoThi[V_ * H_];              // WoutT[v][k]
__device__ __align__(16) __nv_bfloat16 g_WoTlo[V_ * H_];
__device__ __align__(16) __nv_bfloat16 g_h0hi[BH];                    // initial h split
__device__ __align__(16) __nv_bfloat16 g_h0lo[BH];
__device__ __align__(16) __nv_bfloat16 g_Hshi[(size_t)T_ * BH];       // h_t splits (A for t+1, out-GEMM input)
__device__ __align__(16) __nv_bfloat16 g_Hslo[(size_t)T_ * BH];

// ---------------- PTX helpers (plain-sm_100 legal: sm_80-era MMA path) ----------------
__device__ __forceinline__ uint32_t smem_u32(const void* p) {
    uint32_t a;
    asm("{ .reg .u64 t; cvta.to.shared.u64 t, %1; cvt.u32.u64 %0, t; }" : "=r"(a) : "l"(p));
    return a;
}
#define SWZ128(o) ((o) ^ (((o) >> 3) & 0x70))

#define CP16(dst, src) \
    asm volatile("cp.async.cg.shared.global [%0], [%1], 16;" :: "r"(dst), "l"(src))
#define CP_COMMIT() asm volatile("cp.async.commit_group;" ::: "memory")
#define CP_WAIT1()  asm volatile("cp.async.wait_group 1;" ::: "memory")
#define CP_WAIT0()  asm volatile("cp.async.wait_group 0;" ::: "memory")

#define LDSM4(r, addr) \
    asm volatile("ldmatrix.sync.aligned.m8n8.x4.shared.b16 {%0,%1,%2,%3}, [%4];" \
        : "=r"((r)[0]), "=r"((r)[1]), "=r"((r)[2]), "=r"((r)[3]) : "r"(addr))

#define MMA16816(c, a, b0, b1) \
    asm volatile("mma.sync.aligned.m16n8k16.row.col.f32.bf16.bf16.f32 " \
        "{%0,%1,%2,%3}, {%4,%5,%6,%7}, {%8,%9}, {%0,%1,%2,%3};" \
        : "+f"((c)[0]), "+f"((c)[1]), "+f"((c)[2]), "+f"((c)[3]) \
        : "r"((a)[0]), "r"((a)[1]), "r"((a)[2]), "r"((a)[3]), "r"(b0), "r"(b1))

__device__ __forceinline__ void split_bf16(float v, __nv_bfloat16& hi, __nv_bfloat16& lo) {
    hi = __float2bfloat16(v);
    lo = __float2bfloat16(v - __bfloat162float(hi));
}

// ---------------- pack: WxT + WhT bf16 splits (both [n][k]), bias ----------------
__global__ void pack_gates(const float* __restrict__ Wf, const float* __restrict__ Wi,
                           const float* __restrict__ Wo, const float* __restrict__ Wc,
                           const float* __restrict__ bf, const float* __restrict__ bi,
                           const float* __restrict__ bo, const float* __restrict__ bc)
{
    const int totalW = (E_ + H_) * H_;
    int idx = blockIdx.x * blockDim.x + threadIdx.x;
    if (idx < totalW) {
        int k = idx / H_;
        int j = idx % H_;
        float v[4] = {Wf[idx], Wi[idx], Wo[idx], Wc[idx]};
        if (k < E_) {
            #pragma unroll
            for (int g = 0; g < 4; g++) {
                __nv_bfloat16 hi, lo;
                split_bf16(v[g], hi, lo);
                size_t o = (size_t)(j * 4 + g) * E_ + k;
                g_WxThi[o] = hi;
                g_WxTlo[o] = lo;
            }
        } else {
            int kk = k - E_;
            #pragma unroll
            for (int g = 0; g < 4; g++) {
                __nv_bfloat16 hi, lo;
                split_bf16(v[g], hi, lo);
                size_t o = (size_t)(j * 4 + g) * H_ + kk;
                g_WhThi[o] = hi;
                g_WhTlo[o] = lo;
            }
        }
    } else if (idx < totalW + H_) {
        int j = idx - totalW;
        g_bias[j * 4 + 0] = bf[j];
        g_bias[j * 4 + 1] = bi[j];
        g_bias[j * 4 + 2] = bo[j];
        g_bias[j * 4 + 3] = bc[j];
    }
}

__global__ void pack_wout(const float* __restrict__ Wout)
{
    int idx = blockIdx.x * blockDim.x + threadIdx.x;   // over V_*H_
    if (idx < V_ * H_) {
        int v = idx % V_, k = idx / V_;   // Wout[k*V + v]
        __nv_bfloat16 hi, lo;
        split_bf16(Wout[idx], hi, lo);
        size_t o = (size_t)v * H_ + k;
        g_WoThi[o] = hi;
        g_WoTlo[o] = lo;
    }
}

__global__ void split_src(const float* __restrict__ src, __nv_bfloat16* __restrict__ hi,
                          __nv_bfloat16* __restrict__ lo, size_t n)
{
    size_t i = (size_t)blockIdx.x * blockDim.x + threadIdx.x;
    if (i < n) {
        __nv_bfloat16 h, l;
        split_bf16(src[i], h, l);
        hi[i] = h;
        lo[i] = l;
    }
}

// ---------------- init state ----------------
__global__ void init_state(const float* __restrict__ hidden, const float* __restrict__ cell)
{
    int i = blockIdx.x * blockDim.x + threadIdx.x;
    if (i < BH) {
        __nv_bfloat16 hi, lo;
        split_bf16(hidden[i], hi, lo);
        g_h0hi[i] = hi;
        g_h0lo[i] = lo;
        g_c[i]    = cell[i];
    }
    if (i == 0) { g_bar_count = 0; g_bar_gen = 0; }
}

// ---------------- bf16x3 split GEMM on mma.sync tensor cores (unchanged, PASSING) ----
#define STG_BYTES   65536
#define OFF_AHI     0
#define OFF_ALO     16384
#define OFF_BHI     32768
#define OFF_BLO     49152
#define GEMM_SMEM   (2 * STG_BYTES)

__device__ __forceinline__ void stage_fill(
    uint32_t sstage,
    const __nv_bfloat16* __restrict__ Ahi, const __nv_bfloat16* __restrict__ Alo,
    const __nv_bfloat16* __restrict__ Bhi, const __nv_bfloat16* __restrict__ Blo,
    int m0, int n0, int kc, int K, int tid)
{
    #pragma unroll
    for (int i = 0; i < 4; i++) {
        int u  = tid + i * 256;
        int r  = u >> 3;
        int cu = u & 7;
        uint32_t dsw = SWZ128((uint32_t)(r * 128 + cu * 16));
        size_t ao = (size_t)(m0 + r) * K + kc + cu * 8;
        size_t bo = (size_t)(n0 + r) * K + kc + cu * 8;
        CP16(sstage + OFF_AHI + dsw, Ahi + ao);
        CP16(sstage + OFF_ALO + dsw, Alo + ao);
        CP16(sstage + OFF_BHI + dsw, Bhi + bo);
        CP16(sstage + OFF_BLO + dsw, Blo + bo);
    }
}

__global__ __launch_bounds__(256, 1) void gemm_bf16x3(
    const __nv_bfloat16* __restrict__ Ahi, const __nv_bfloat16* __restrict__ Alo,
    const __nv_bfloat16* __restrict__ Bhi, const __nv_bfloat16* __restrict__ Blo,
    const float* __restrict__ bias, float* __restrict__ C,
    int K, int ldc)
{
    extern __shared__ char smem[];
    const uint32_t sbase = smem_u32(smem);
    const int tid  = threadIdx.x;
    const int lane = tid & 31;
    const int w    = tid >> 5;
    const int wm   = w & 3;
    const int wn   = w >> 2;
    const int m0 = blockIdx.y * 128;
    const int n0 = blockIdx.x * 128;
    const int NC = K / 64;

    float acc[2][8][4];
    #pragma unroll
    for (int mt = 0; mt < 2; mt++)
        #pragma unroll
        for (int nt = 0; nt < 8; nt++)
            #pragma unroll
            for (int q = 0; q < 4; q++) acc[mt][nt][q] = 0.f;

    stage_fill(sbase, Ahi, Alo, Bhi, Blo, m0, n0, 0, K, tid);
    CP_COMMIT();

    const int a_row = (lane & 15);
    const int a_cuh = (lane >> 4);
    const int b_row = (lane & 7) + ((lane >> 4) << 3);
    const int b_cuh = ((lane >> 3) & 1);

    #pragma unroll 1
    for (int c = 0; c < NC; c++) {
        if (c + 1 < NC) {
            stage_fill(sbase + ((c + 1) & 1) * STG_BYTES, Ahi, Alo, Bhi, Blo,
                       m0, n0, (c + 1) * 64, K, tid);
            CP_COMMIT();
            CP_WAIT1();
        } else {
            CP_WAIT0();
        }
        __syncthreads();

        const uint32_t sS = sbase + (c & 1) * STG_BYTES;

        #pragma unroll
        for (int ks = 0; ks < 4; ks++) {
            uint32_t aH[2][4], aL[2][4], bH[4][4], bL[4][4];
            #pragma unroll
            for (int mt = 0; mt < 2; mt++) {
                int row = wm * 32 + mt * 16 + a_row;
                int cu  = ks * 2 + a_cuh;
                uint32_t off = SWZ128((uint32_t)(row * 128 + cu * 16));
                LDSM4(aH[mt], sS + OFF_AHI + off);
                LDSM4(aL[mt], sS + OFF_ALO + off);
            }
            #pragma unroll
            for (int np = 0; np < 4; np++) {
                int row = wn * 64 + np * 16 + b_row;
                int cu  = ks * 2 + b_cuh;
                uint32_t off = SWZ128((uint32_t)(row * 128 + cu * 16));
                LDSM4(bH[np], sS + OFF_BHI + off);
                LDSM4(bL[np], sS + OFF_BLO + off);
            }
            #pragma unroll
            for (int mt = 0; mt < 2; mt++)
                #pragma unroll
                for (int np = 0; np < 4; np++) {
                    MMA16816(acc[mt][2 * np],     aH[mt], bH[np][0], bH[np][1]);
                    MMA16816(acc[mt][2 * np + 1], aH[mt], bH[np][2], bH[np][3]);
                    MMA16816(acc[mt][2 * np],     aL[mt], bH[np][0], bH[np][1]);
                    MMA16816(acc[mt][2 * np + 1], aL[mt], bH[np][2], bH[np][3]);
                    MMA16816(acc[mt][2 * np],     aH[mt], bL[np][0], bL[np][1]);
                    MMA16816(acc[mt][2 * np + 1], aH[mt], bL[np][2], bL[np][3]);
                }
        }
        __syncthreads();
    }

    #pragma unroll
    for (int mt = 0; mt < 2; mt++) {
        int rbase = m0 + wm * 32 + mt * 16 + (lane >> 2);
        #pragma unroll
        for (int nt = 0; nt < 8; nt++) {
            int col = n0 + wn * 64 + nt * 8 + (lane & 3) * 2;
            float2 bv = *(const float2*)&bias[col];
            float2 v0, v1;
            v0.x = acc[mt][nt][0] + bv.x;
            v0.y = acc[mt][nt][1] + bv.y;
            v1.x = acc[mt][nt][2] + bv.x;
            v1.y = acc[mt][nt][3] + bv.y;
            *(float2*)&C[(size_t)rbase * ldc + col]       = v0;
            *(float2*)&C[(size_t)(rbase + 8) * ldc + col] = v1;
        }
    }
}

// ---------------- persistent tensor-core LSTM recurrence ----------------
// 128 CTAs x 256 threads. CTA owns 32 gate-cols (8 hidden units).
// Per step: gates[64,32] = h[64,1024] @ WhT_tile^T (bf16x3 via mma.sync) + Xproj;
// fused gate epilogue writes c and split h (Hshi/Hslo = next A + out-GEMM input).
#define RSTG        24576                // per-stage: Ahi 8K | Alo 8K | Bhi 4K | Blo 4K
#define R_AHI       0
#define R_ALO       8192
#define R_BHI       16384
#define R_BLO       20480
#define R_SGATE     (2 * RSTG)           // 8 KB fp32 [64][32]
#define REC_SMEM    (2 * RSTG + 8192)

__global__ __launch_bounds__(256, 1) void lstm_mma_persistent()
{
    extern __shared__ char smem[];
    const uint32_t sbase = smem_u32(smem);
    float* sgate = (float*)(smem + R_SGATE);

    const int tid  = threadIdx.x;
    const int lane = tid & 31;
    const int w    = tid >> 5;
    const int wm   = w & 1;          // m offset wm*32
    const int wn   = w >> 1;         // n offset wn*8
    const int n0   = blockIdx.x * 32;

    const int a_row = (lane & 15);
    const int a_cuh = (lane >> 4);         // 0/1
    const int b_row = (lane & 7);          // n-row within n8
    const int b_cu4 = ((lane >> 3) & 3);   // 0..3: k8 subtile within k32

    for (int t = 0; t < T_; t++) {
        const __nv_bfloat16* Ahi_t = (t == 0) ? g_h0hi : g_Hshi + (size_t)(t - 1) * BH;
        const __nv_bfloat16* Alo_t = (t == 0) ? g_h0lo : g_Hslo + (size_t)(t - 1) * BH;

        float acc[2][4];
        #pragma unroll
        for (int mt = 0; mt < 2; mt++)
            #pragma unroll
            for (int q = 0; q < 4; q++) acc[mt][q] = 0.f;

        // ---- prologue fill chunk 0 ----
        {
            #pragma unroll
            for (int i = 0; i < 2; i++) {
                int u = tid + i * 256;         // 0..511: A tiles 64 rows x 8 cu
                int r = u >> 3, cu = u & 7;
                uint32_t dsw = SWZ128((uint32_t)(r * 128 + cu * 16));
                CP16(sbase + R_AHI + dsw, Ahi_t + (size_t)r * H_ + cu * 8);
                CP16(sbase + R_ALO + dsw, Alo_t + (size_t)r * H_ + cu * 8);
            }
            {
                int r = tid >> 3, cu = tid & 7;   // B tiles 32 rows x 8 cu
                uint32_t dsw = SWZ128((uint32_t)(r * 128 + cu * 16));
                CP16(sbase + R_BHI + dsw, g_WhThi + (size_t)(n0 + r) * H_ + cu * 8);
                CP16(sbase + R_BLO + dsw, g_WhTlo + (size_t)(n0 + r) * H_ + cu * 8);
            }
            CP_COMMIT();
        }

        #pragma unroll 1
        for (int c = 0; c < H_ / 64; c++) {
            if (c + 1 < H_ / 64) {
                uint32_t sN = sbase + ((c + 1) & 1) * RSTG;
                int kc = (c + 1) * 64;
                #pragma unroll
                for (int i = 0; i < 2; i++) {
                    int u = tid + i * 256;
                    int r = u >> 3, cu = u & 7;
                    uint32_t dsw = SWZ128((uint32_t)(r * 128 + cu * 16));
                    CP16(sN + R_AHI + dsw, Ahi_t + (size_t)r * H_ + kc + cu * 8);
                    CP16(sN + R_ALO + dsw, Alo_t + (size_t)r * H_ + kc + cu * 8);
                }
                {
                    int r = tid >> 3, cu = tid & 7;
                    uint32_t dsw = SWZ128((uint32_t)(r * 128 + cu * 16));
                    CP16(sN + R_BHI + dsw, g_WhThi + (size_t)(n0 + r) * H_ + kc + cu * 8);
                    CP16(sN + R_BLO + dsw, g_WhTlo + (size_t)(n0 + r) * H_ + kc + cu * 8);
                }
                CP_COMMIT();
                CP_WAIT1();
            } else {
                CP_WAIT0();
            }
            __syncthreads();

            const uint32_t sS = sbase + (c & 1) * RSTG;

            #pragma unroll
            for (int ks2 = 0; ks2 < 2; ks2++) {
                // B frags: n8 x k32 (4 regs = 4 k8 subtiles)
                uint32_t bH[4], bL[4];
                {
                    int row = wn * 8 + b_row;
                    int cu  = ks2 * 4 + b_cu4;
                    uint32_t off = SWZ128((uint32_t)(row * 128 + cu * 16));
                    LDSM4(bH, sS + R_BHI + off);
                    LDSM4(bL, sS + R_BLO + off);
                }
                #pragma unroll
                for (int ks = 0; ks < 2; ks++) {
                    uint32_t aH[2][4], aL[2][4];
                    #pragma unroll
                    for (int mt = 0; mt < 2; mt++) {
                        int row = wm * 32 + mt * 16 + a_row;
                        int cu  = ks2 * 4 + ks * 2 + a_cuh;
                        uint32_t off = SWZ128((uint32_t)(row * 128 + cu * 16));
                        LDSM4(aH[mt], sS + R_AHI + off);
                        LDSM4(aL[mt], sS + R_ALO + off);
                    }
                    #pragma unroll
                    for (int mt = 0; mt < 2; mt++) {
                        MMA16816(acc[mt], aH[mt], bH[2 * ks], bH[2 * ks + 1]);
                        MMA16816(acc[mt], aL[mt], bH[2 * ks], bH[2 * ks + 1]);
                        MMA16816(acc[mt], aH[mt], bL[2 * ks], bL[2 * ks + 1]);
                    }
                }
            }
            __syncthreads();
        }

        // ---- stage preacts to smem so each thread can gather a full gate quad ----
        #pragma unroll
        for (int mt = 0; mt < 2; mt++) {
            int r0 = wm * 32 + mt * 16 + (lane >> 2);
            int cb = wn * 8 + (lane & 3) * 2;
            sgate[r0 * 32 + cb]            = acc[mt][0];
            sgate[r0 * 32 + cb + 1]        = acc[mt][1];
            sgate[(r0 + 8) * 32 + cb]      = acc[mt][2];
            sgate[(r0 + 8) * 32 + cb + 1]  = acc[mt][3];
        }
        __syncthreads();

        // ---- fused LSTM gate epilogue: 512 (b, j) pairs over 256 threads ----
        const float* xp_t = g_Xproj + (size_t)t * B_ * G4;
        #pragma unroll
        for (int q = 0; q < 2; q++) {
            int idx = tid + q * 256;       // 0..511
            int b  = idx >> 3;
            int jl = idx & 7;
            int j  = (n0 >> 2) + jl;
            float pf = sgate[b * 32 + jl * 4 + 0];
            float pi = sgate[b * 32 + jl * 4 + 1];
            float po = sgate[b * 32 + jl * 4 + 2];
            float pc = sgate[b * 32 + jl * 4 + 3];
            float4 xp = *(const float4*)&xp_t[(size_t)b * G4 + n0 + jl * 4];
            pf += xp.x; pi += xp.y; po += xp.z; pc += xp.w;
            float fg = 1.f / (1.f + expf(-pf));
            float ig = 1.f / (1.f + expf(-pi));
            float og = 1.f / (1.f + expf(-po));
            float ct = tanhf(pc);
            float cnew = fg * g_c[b * H_ + j] + ig * ct;
            float hnew = og * tanhf(cnew);
            g_c[b * H_ + j] = cnew;
            __nv_bfloat16 hhi, hlo;
            split_bf16(hnew, hhi, hlo);
            size_t ho = (size_t)t * BH + (size_t)b * H_ + j;
            g_Hshi[ho] = hhi;
            g_Hslo[ho] = hlo;
        }

        // ---- device-wide barrier: release step t ----
        __threadfence();
        __syncthreads();
        if (tid == 0) {
            unsigned old = atomicAdd(&g_bar_count, 1);
            if (old == (unsigned)(gridDim.x - 1)) {
                g_bar_count = 0;
                __threadfence();
                atomicExch(&g_bar_gen, (unsigned)(t + 1));
            } else {
                while (atomicAdd(&g_bar_gen, 0u) < (unsigned)(t + 1)) { }
            }
            __threadfence();
        }
        __syncthreads();
    }
}

// ---------------- final h / c copy (h reconstructed from splits) ----------------
__global__ void write_hc(float* __restrict__ dst)
{
    int i = blockIdx.x * blockDim.x + threadIdx.x;
    if (i < BH) {
        size_t o = (size_t)(T_ - 1) * BH + i;
        dst[i]      = __bfloat162float(g_Hshi[o]) + __bfloat162float(g_Hslo[o]);
        dst[BH + i] = g_c[i];
    }
}

// ---------------- launch ----------------
extern "C" void kernel_launch(void* const* d_in, const int* in_sizes, int n_in,
                              void* d_out, int out_size)
{
    const float* input_seq = (const float*)d_in[0];
    const float* hidden    = (const float*)d_in[1];
    const float* cell      = (const float*)d_in[2];
    const float* Wf        = (const float*)d_in[3];
    const float* bf        = (const float*)d_in[4];
    const float* Wi        = (const float*)d_in[5];
    const float* bi        = (const float*)d_in[6];
    const float* Wo        = (const float*)d_in[7];
    const float* bo        = (const float*)d_in[8];
    const float* Wc        = (const float*)d_in[9];
    const float* bc        = (const float*)d_in[10];
    const float* Wout      = (const float*)d_in[11];
    const float* bout      = (const float*)d_in[12];
    float* out = (float*)d_out;

    // idempotent, non-stream-ordered; called unconditionally (no static guards)
    cudaFuncSetAttribute(gemm_bf16x3, cudaFuncAttributeMaxDynamicSharedMemorySize, GEMM_SMEM);
    cudaFuncSetAttribute(lstm_mma_persistent, cudaFuncAttributeMaxDynamicSharedMemorySize, REC_SMEM);

    float *pBias, *pX;
    __nv_bfloat16 *pAhi, *pAlo, *pWxh, *pWxl, *pWoh, *pWol, *pHsh, *pHsl;
    cudaGetSymbolAddress((void**)&pBias, g_bias);
    cudaGetSymbolAddress((void**)&pX,    g_Xproj);
    cudaGetSymbolAddress((void**)&pAhi,  g_Ahi);
    cudaGetSymbolAddress((void**)&pAlo,  g_Alo);
    cudaGetSymbolAddress((void**)&pWxh,  g_WxThi);
    cudaGetSymbolAddress((void**)&pWxl,  g_WxTlo);
    cudaGetSymbolAddress((void**)&pWoh,  g_WoThi);
    cudaGetSymbolAddress((void**)&pWol,  g_WoTlo);
    cudaGetSymbolAddress((void**)&pHsh,  g_Hshi);
    cudaGetSymbolAddress((void**)&pHsl,  g_Hslo);

    // 1. packs + splits
    {
        int total = (E_ + H_) * H_ + H_;
        pack_gates<<<(total + 255) / 256, 256>>>(Wf, Wi, Wo, Wc, bf, bi, bo, bc);
    }
    pack_wout<<<(V_ * H_ + 255) / 256, 256>>>(Wout);
    {
        size_t n = (size_t)T_ * B_ * E_;
        split_src<<<(int)((n + 255) / 256), 256>>>(input_seq, pAhi, pAlo, n);
    }
    init_state<<<(BH + 255) / 256, 256>>>(hidden, cell);

    // 2. Xproj = A @ WxT^T + bias  on tensor cores (M=32768, N=4096, K=512)
    {
        dim3 grid(G4 / 128, (T_ * B_) / 128);
        gemm_bf16x3<<<grid, 256, GEMM_SMEM>>>(pAhi, pAlo, pWxh, pWxl, pBias, pX, E_, G4);
    }

    // 3. recurrence: persistent tensor-core kernel (writes Hshi/Hslo directly)
    lstm_mma_persistent<<<NCTA_STEP, 256, REC_SMEM>>>();

    // 4. out GEMM (M=32768, N=256, K=1024) straight from split hseq
    {
        dim3 grid(V_ / 128, (T_ * B_) / 128);
        gemm_bf16x3<<<grid, 256, GEMM_SMEM>>>(pHsh, pHsl, pWoh, pWol, bout, out, H_, V_);
    }

    // 5. final h, c
    write_hc<<<(BH + 255) / 256, 256>>>(out + (size_t)T_ * B_ * V_);
}

// round 9
// speedup vs baseline: 4.7489x; 1.1899x over previous
#include <cuda_runtime.h>
#include <cuda_bf16.h>
#include <math.h>
#include <stdint.h>

// Problem dims
#define T_  512
#define B_  64
#define E_  512
#define H_  1024
#define V_  256
#define G4  4096   // 4*H gate-interleaved: col n = 4*j + g

#define NCTA_STEP 128
#define BH  (B_ * H_)

// ---------------- scratch (device globals; allocation-free) ----------------
__device__ float g_bias[G4];
__device__ float g_Xproj[(size_t)T_ * B_ * G4];       // 512 MB
__device__ float g_c[B_ * H_];
__device__ unsigned g_bar_count;
__device__ unsigned g_bar_gen;

// bf16 split operands (16B aligned)
__device__ __align__(16) __nv_bfloat16 g_Ahi[(size_t)T_ * B_ * E_];
__device__ __align__(16) __nv_bfloat16 g_Alo[(size_t)T_ * B_ * E_];
__device__ __align__(16) __nv_bfloat16 g_WxThi[G4 * E_];              // WxT[n][k]
__device__ __align__(16) __nv_bfloat16 g_WxTlo[G4 * E_];
__device__ __align__(16) __nv_bfloat16 g_WhThi[G4 * H_];              // WhT[n][k]
__device__ __align__(16) __nv_bfloat16 g_WhTlo[G4 * H_];
__device__ __align__(16) __nv_bfloat16 g_WoThi[V_ * H_];              // WoT[v][k]
__device__ __align__(16) __nv_bfloat16 g_WoTlo[V_ * H_];
__device__ __align__(16) __nv_bfloat16 g_h0hi[BH];
__device__ __align__(16) __nv_bfloat16 g_h0lo[BH];
__device__ __align__(16) __nv_bfloat16 g_Hshi[(size_t)T_ * BH];
__device__ __align__(16) __nv_bfloat16 g_Hslo[(size_t)T_ * BH];

// ---------------- PTX helpers (plain-sm_100 legal) ----------------
__device__ __forceinline__ uint32_t smem_u32(const void* p) {
    uint32_t a;
    asm("{ .reg .u64 t; cvta.to.shared.u64 t, %1; cvt.u32.u64 %0, t; }" : "=r"(a) : "l"(p));
    return a;
}
#define SWZ128(o) ((o) ^ (((o) >> 3) & 0x70))

#define CP16(dst, src) \
    asm volatile("cp.async.cg.shared.global [%0], [%1], 16;" :: "r"(dst), "l"(src))
#define CP_COMMIT() asm volatile("cp.async.commit_group;" ::: "memory")
#define CP_WAIT1()  asm volatile("cp.async.wait_group 1;" ::: "memory")
#define CP_WAIT0()  asm volatile("cp.async.wait_group 0;" ::: "memory")

#define LDSM4(r, addr) \
    asm volatile("ldmatrix.sync.aligned.m8n8.x4.shared.b16 {%0,%1,%2,%3}, [%4];" \
        : "=r"((r)[0]), "=r"((r)[1]), "=r"((r)[2]), "=r"((r)[3]) : "r"(addr))

#define MMA16816(c, a, b0, b1) \
    asm volatile("mma.sync.aligned.m16n8k16.row.col.f32.bf16.bf16.f32 " \
        "{%0,%1,%2,%3}, {%4,%5,%6,%7}, {%8,%9}, {%0,%1,%2,%3};" \
        : "+f"((c)[0]), "+f"((c)[1]), "+f"((c)[2]), "+f"((c)[3]) \
        : "r"((a)[0]), "r"((a)[1]), "r"((a)[2]), "r"((a)[3]), "r"(b0), "r"(b1))

__device__ __forceinline__ void split_bf16(float v, __nv_bfloat16& hi, __nv_bfloat16& lo) {
    hi = __float2bfloat16(v);
    lo = __float2bfloat16(v - __bfloat162float(hi));
}

// ---------------- packs: smem-tiled transposes (coalesced both sides) ----------------
__global__ __launch_bounds__(256) void pack_gates_t(
    const float* __restrict__ Wf, const float* __restrict__ Wi,
    const float* __restrict__ Wo, const float* __restrict__ Wc)
{
    __shared__ float tile[4][32][33];
    const int tid = threadIdx.x;
    const int jt  = blockIdx.x & 31;          // j tile (H/32 = 32)
    const int kt  = blockIdx.x >> 5;          // k tile ((E+H)/32 = 48)
    const int k0  = kt * 32, j0 = jt * 32;

    const float* W[4] = {Wf, Wi, Wo, Wc};
    #pragma unroll
    for (int g = 0; g < 4; g++)
        #pragma unroll
        for (int i = 0; i < 4; i++) {
            int u = tid + i * 256;            // 0..1023
            int r = u >> 5, c = u & 31;
            tile[g][r][c] = W[g][(size_t)(k0 + r) * H_ + j0 + c];
        }
    __syncthreads();

    const bool isWx = (k0 < E_);
    const int kb = isWx ? k0 : (k0 - E_);
    const int K  = isWx ? E_ : H_;
    __nv_bfloat16* Dh = isWx ? g_WxThi : g_WhThi;
    __nv_bfloat16* Dl = isWx ? g_WxTlo : g_WhTlo;

    #pragma unroll
    for (int i = 0; i < 16; i++) {
        int rowu = (tid >> 5) + i * 8;        // 0..127 output rows within tile
        int g  = rowu & 3;
        int jj = rowu >> 2;
        int kk = tid & 31;
        float v = tile[g][kk][jj];
        __nv_bfloat16 hi, lo;
        split_bf16(v, hi, lo);
        size_t o = (size_t)((j0 + jj) * 4 + g) * K + kb + kk;
        Dh[o] = hi;
        Dl[o] = lo;
    }
}

// Wout [H][V] row-major -> WoT[v][k]
__global__ __launch_bounds__(256) void pack_wout_t(const float* __restrict__ Wout)
{
    __shared__ float tile[32][33];
    const int tid = threadIdx.x;
    const int vt  = blockIdx.x & 7;           // V/32 = 8
    const int kt  = blockIdx.x >> 3;          // H/32 = 32
    const int k0  = kt * 32, v0 = vt * 32;

    #pragma unroll
    for (int i = 0; i < 4; i++) {
        int u = tid + i * 256;
        int r = u >> 5, c = u & 31;
        tile[r][c] = Wout[(size_t)(k0 + r) * V_ + v0 + c];
    }
    __syncthreads();

    #pragma unroll
    for (int i = 0; i < 4; i++) {
        int u = tid + i * 256;
        int vv = u >> 5, kk = u & 31;
        float val = tile[kk][vv];
        __nv_bfloat16 hi, lo;
        split_bf16(val, hi, lo);
        size_t o = (size_t)(v0 + vv) * H_ + k0 + kk;
        g_WoThi[o] = hi;
        g_WoTlo[o] = lo;
    }
}

__global__ void split_src(const float* __restrict__ src, __nv_bfloat16* __restrict__ hi,
                          __nv_bfloat16* __restrict__ lo, size_t n)
{
    size_t i = (size_t)blockIdx.x * blockDim.x + threadIdx.x;
    if (i < n) {
        __nv_bfloat16 h, l;
        split_bf16(src[i], h, l);
        hi[i] = h;
        lo[i] = l;
    }
}

// ---------------- init state (+ bias pack) ----------------
__global__ void init_state(const float* __restrict__ hidden, const float* __restrict__ cell,
                           const float* __restrict__ bf, const float* __restrict__ bi,
                           const float* __restrict__ bo, const float* __restrict__ bc)
{
    int i = blockIdx.x * blockDim.x + threadIdx.x;
    if (i < BH) {
        __nv_bfloat16 hi, lo;
        split_bf16(hidden[i], hi, lo);
        g_h0hi[i] = hi;
        g_h0lo[i] = lo;
        g_c[i]    = cell[i];
    }
    if (i < H_) {
        g_bias[i * 4 + 0] = bf[i];
        g_bias[i * 4 + 1] = bi[i];
        g_bias[i * 4 + 2] = bo[i];
        g_bias[i * 4 + 3] = bc[i];
    }
    if (i == 0) { g_bar_count = 0; g_bar_gen = 0; }
}

// ---------------- bf16x3 split GEMM: CTA tile 64x128, 4 warps, 2 CTAs/SM ----------------
#define STG_BYTES   49152
#define OFF_AHI     0
#define OFF_ALO     8192
#define OFF_BHI     16384
#define OFF_BLO     32768
#define GEMM_SMEM   (2 * STG_BYTES)

__device__ __forceinline__ void stage_fill(
    uint32_t sstage,
    const __nv_bfloat16* __restrict__ Ahi, const __nv_bfloat16* __restrict__ Alo,
    const __nv_bfloat16* __restrict__ Bhi, const __nv_bfloat16* __restrict__ Blo,
    int m0, int n0, int kc, int K, int tid)
{
    #pragma unroll
    for (int i = 0; i < 4; i++) {             // A: 64 rows x 8 cu
        int u  = tid + i * 128;
        int r  = u >> 3;
        int cu = u & 7;
        uint32_t dsw = SWZ128((uint32_t)(r * 128 + cu * 16));
        size_t ao = (size_t)(m0 + r) * K + kc + cu * 8;
        CP16(sstage + OFF_AHI + dsw, Ahi + ao);
        CP16(sstage + OFF_ALO + dsw, Alo + ao);
    }
    #pragma unroll
    for (int i = 0; i < 8; i++) {             // B: 128 rows x 8 cu
        int u  = tid + i * 128;
        int r  = u >> 3;
        int cu = u & 7;
        uint32_t dsw = SWZ128((uint32_t)(r * 128 + cu * 16));
        size_t bo = (size_t)(n0 + r) * K + kc + cu * 8;
        CP16(sstage + OFF_BHI + dsw, Bhi + bo);
        CP16(sstage + OFF_BLO + dsw, Blo + bo);
    }
}

__global__ __launch_bounds__(128, 2) void gemm_bf16x3(
    const __nv_bfloat16* __restrict__ Ahi, const __nv_bfloat16* __restrict__ Alo,
    const __nv_bfloat16* __restrict__ Bhi, const __nv_bfloat16* __restrict__ Blo,
    const float* __restrict__ bias, float* __restrict__ C,
    int K, int ldc)
{
    extern __shared__ char smem[];
    const uint32_t sbase = smem_u32(smem);
    const int tid  = threadIdx.x;
    const int lane = tid & 31;
    const int w    = tid >> 5;
    const int wm   = w & 1;          // m offset wm*32
    const int wn   = w >> 1;         // n offset wn*64
    const int m0 = blockIdx.y * 64;
    const int n0 = blockIdx.x * 128;
    const int NC = K / 64;

    float acc[2][8][4];
    #pragma unroll
    for (int mt = 0; mt < 2; mt++)
        #pragma unroll
        for (int nt = 0; nt < 8; nt++)
            #pragma unroll
            for (int q = 0; q < 4; q++) acc[mt][nt][q] = 0.f;

    stage_fill(sbase, Ahi, Alo, Bhi, Blo, m0, n0, 0, K, tid);
    CP_COMMIT();

    const int a_row = (lane & 15);
    const int a_cuh = (lane >> 4);
    const int b_row = (lane & 7) + ((lane >> 4) << 3);
    const int b_cuh = ((lane >> 3) & 1);

    #pragma unroll 1
    for (int c = 0; c < NC; c++) {
        if (c + 1 < NC) {
            stage_fill(sbase + ((c + 1) & 1) * STG_BYTES, Ahi, Alo, Bhi, Blo,
                       m0, n0, (c + 1) * 64, K, tid);
            CP_COMMIT();
            CP_WAIT1();
        } else {
            CP_WAIT0();
        }
        __syncthreads();

        const uint32_t sS = sbase + (c & 1) * STG_BYTES;

        #pragma unroll
        for (int ks = 0; ks < 4; ks++) {
            uint32_t aH[2][4], aL[2][4], bH[4][4], bL[4][4];
            #pragma unroll
            for (int mt = 0; mt < 2; mt++) {
                int row = wm * 32 + mt * 16 + a_row;
                int cu  = ks * 2 + a_cuh;
                uint32_t off = SWZ128((uint32_t)(row * 128 + cu * 16));
                LDSM4(aH[mt], sS + OFF_AHI + off);
                LDSM4(aL[mt], sS + OFF_ALO + off);
            }
            #pragma unroll
            for (int np = 0; np < 4; np++) {
                int row = wn * 64 + np * 16 + b_row;
                int cu  = ks * 2 + b_cuh;
                uint32_t off = SWZ128((uint32_t)(row * 128 + cu * 16));
                LDSM4(bH[np], sS + OFF_BHI + off);
                LDSM4(bL[np], sS + OFF_BLO + off);
            }
            #pragma unroll
            for (int mt = 0; mt < 2; mt++)
                #pragma unroll
                for (int np = 0; np < 4; np++) {
                    MMA16816(acc[mt][2 * np],     aH[mt], bH[np][0], bH[np][1]);
                    MMA16816(acc[mt][2 * np + 1], aH[mt], bH[np][2], bH[np][3]);
                    MMA16816(acc[mt][2 * np],     aL[mt], bH[np][0], bH[np][1]);
                    MMA16816(acc[mt][2 * np + 1], aL[mt], bH[np][2], bH[np][3]);
                    MMA16816(acc[mt][2 * np],     aH[mt], bL[np][0], bL[np][1]);
                    MMA16816(acc[mt][2 * np + 1], aH[mt], bL[np][2], bL[np][3]);
                }
        }
        __syncthreads();
    }

    #pragma unroll
    for (int mt = 0; mt < 2; mt++) {
        int rbase = m0 + wm * 32 + mt * 16 + (lane >> 2);
        #pragma unroll
        for (int nt = 0; nt < 8; nt++) {
            int col = n0 + wn * 64 + nt * 8 + (lane & 3) * 2;
            float2 bv = *(const float2*)&bias[col];
            float2 v0, v1;
            v0.x = acc[mt][nt][0] + bv.x;
            v0.y = acc[mt][nt][1] + bv.y;
            v1.x = acc[mt][nt][2] + bv.x;
            v1.y = acc[mt][nt][3] + bv.y;
            *(float2*)&C[(size_t)rbase * ldc + col]       = v0;
            *(float2*)&C[(size_t)(rbase + 8) * ldc + col] = v1;
        }
    }
}

// ---------------- persistent tensor-core LSTM recurrence ----------------
#define RSTG        49152                // A-hi 16K | A-lo 16K | B-hi 8K | B-lo 8K
#define R_AHI       0
#define R_ALO       16384
#define R_BHI       32768
#define R_BLO       40960
#define R_SGATE     (2 * RSTG)           // 8 KB fp32 [64][32]
#define REC_SMEM    (2 * RSTG + 8192)

__global__ __launch_bounds__(256, 1) void lstm_mma_persistent()
{
    extern __shared__ char smem[];
    const uint32_t sbase = smem_u32(smem);
    float* sgate = (float*)(smem + R_SGATE);

    const int tid  = threadIdx.x;
    const int lane = tid & 31;
    const int w    = tid >> 5;
    const int wm   = w & 1;          // m offset wm*32
    const int wn   = w >> 1;         // n offset wn*8
    const int n0   = blockIdx.x * 32;

    const int a_row = (lane & 15);
    const int a_cuh = (lane >> 4);
    const int b_row = (lane & 7);
    const int b_cu4 = ((lane >> 3) & 3);

    // epilogue ownership (fixed across steps): idx q -> (b, j)
    int eb[2], ej[2];
    float cv[2];
    #pragma unroll
    for (int q = 0; q < 2; q++) {
        int idx = tid + q * 256;
        eb[q] = idx >> 3;
        ej[q] = (n0 >> 2) + (idx & 7);
        cv[q] = g_c[eb[q] * H_ + ej[q]];
    }

    for (int t = 0; t < T_; t++) {
        const __nv_bfloat16* Ahi_t = (t == 0) ? g_h0hi : g_Hshi + (size_t)(t - 1) * BH;
        const __nv_bfloat16* Alo_t = (t == 0) ? g_h0lo : g_Hslo + (size_t)(t - 1) * BH;
        const float* xp_t = g_Xproj + (size_t)t * B_ * G4;

        // prefetch per-step epilogue operands (hidden under mainloop)
        float4 xpv[2];
        #pragma unroll
        for (int q = 0; q < 2; q++) {
            int jl = (tid + q * 256) & 7;
            xpv[q] = *(const float4*)&xp_t[(size_t)eb[q] * G4 + n0 + jl * 4];
        }

        float acc[2][4];
        #pragma unroll
        for (int mt = 0; mt < 2; mt++)
            #pragma unroll
            for (int q = 0; q < 4; q++) acc[mt][q] = 0.f;

        // ---- prologue fill chunk 0 (128 k) ----
        {
            #pragma unroll
            for (int i = 0; i < 4; i++) {             // A: 64 rows x 16 cu
                int u = tid + i * 256;
                int r = u >> 4, cu = u & 15;
                int s = cu >> 3, c8 = cu & 7;
                uint32_t dsw = (uint32_t)(s * 8192) + SWZ128((uint32_t)(r * 128 + c8 * 16));
                CP16(sbase + R_AHI + dsw, Ahi_t + (size_t)r * H_ + cu * 8);
                CP16(sbase + R_ALO + dsw, Alo_t + (size_t)r * H_ + cu * 8);
            }
            #pragma unroll
            for (int i = 0; i < 2; i++) {             // B: 32 rows x 16 cu
                int u = tid + i * 256;
                int r = u >> 4, cu = u & 15;
                int s = cu >> 3, c8 = cu & 7;
                uint32_t dsw = (uint32_t)(s * 4096) + SWZ128((uint32_t)(r * 128 + c8 * 16));
                CP16(sbase + R_BHI + dsw, g_WhThi + (size_t)(n0 + r) * H_ + cu * 8);
                CP16(sbase + R_BLO + dsw, g_WhTlo + (size_t)(n0 + r) * H_ + cu * 8);
            }
            CP_COMMIT();
        }

        #pragma unroll 1
        for (int c = 0; c < H_ / 128; c++) {
            if (c + 1 < H_ / 128) {
                uint32_t sN = sbase + ((c + 1) & 1) * RSTG;
                int kc = (c + 1) * 128;
                #pragma unroll
                for (int i = 0; i < 4; i++) {
                    int u = tid + i * 256;
                    int r = u >> 4, cu = u & 15;
                    int s = cu >> 3, c8 = cu & 7;
                    uint32_t dsw = (uint32_t)(s * 8192) + SWZ128((uint32_t)(r * 128 + c8 * 16));
                    CP16(sN + R_AHI + dsw, Ahi_t + (size_t)r * H_ + kc + cu * 8);
                    CP16(sN + R_ALO + dsw, Alo_t + (size_t)r * H_ + kc + cu * 8);
                }
                #pragma unroll
                for (int i = 0; i < 2; i++) {
                    int u = tid + i * 256;
                    int r = u >> 4, cu = u & 15;
                    int s = cu >> 3, c8 = cu & 7;
                    uint32_t dsw = (uint32_t)(s * 4096) + SWZ128((uint32_t)(r * 128 + c8 * 16));
                    CP16(sN + R_BHI + dsw, g_WhThi + (size_t)(n0 + r) * H_ + kc + cu * 8);
                    CP16(sN + R_BLO + dsw, g_WhTlo + (size_t)(n0 + r) * H_ + kc + cu * 8);
                }
                CP_COMMIT();
                CP_WAIT1();
            } else {
                CP_WAIT0();
            }
            __syncthreads();

            const uint32_t sS = sbase + (c & 1) * RSTG;

            #pragma unroll
            for (int s = 0; s < 2; s++) {             // 64-k sub-tile
                const uint32_t aB  = sS + R_AHI + s * 8192;
                const uint32_t alB = sS + R_ALO + s * 8192;
                const uint32_t bB  = sS + R_BHI + s * 4096;
                const uint32_t blB = sS + R_BLO + s * 4096;

                #pragma unroll
                for (int ks2 = 0; ks2 < 2; ks2++) {
                    uint32_t bH[4], bL[4];
                    {
                        int row = wn * 8 + b_row;
                        int cu  = ks2 * 4 + b_cu4;
                        uint32_t off = SWZ128((uint32_t)(row * 128 + cu * 16));
                        LDSM4(bH, bB + off);
                        LDSM4(bL, blB + off);
                    }
                    #pragma unroll
                    for (int ks = 0; ks < 2; ks++) {
                        uint32_t aH[2][4], aL[2][4];
                        #pragma unroll
                        for (int mt = 0; mt < 2; mt++) {
                            int row = wm * 32 + mt * 16 + a_row;
                            int cu  = ks2 * 4 + ks * 2 + a_cuh;
                            uint32_t off = SWZ128((uint32_t)(row * 128 + cu * 16));
                            LDSM4(aH[mt], aB + off);
                            LDSM4(aL[mt], alB + off);
                        }
                        #pragma unroll
                        for (int mt = 0; mt < 2; mt++) {
                            MMA16816(acc[mt], aH[mt], bH[2 * ks], bH[2 * ks + 1]);
                            MMA16816(acc[mt], aL[mt], bH[2 * ks], bH[2 * ks + 1]);
                            MMA16816(acc[mt], aH[mt], bL[2 * ks], bL[2 * ks + 1]);
                        }
                    }
                }
            }
            __syncthreads();
        }

        // ---- stage preacts to smem so each thread gathers a full gate quad ----
        #pragma unroll
        for (int mt = 0; mt < 2; mt++) {
            int r0 = wm * 32 + mt * 16 + (lane >> 2);
            int cb = wn * 8 + (lane & 3) * 2;
            sgate[r0 * 32 + cb]            = acc[mt][0];
            sgate[r0 * 32 + cb + 1]        = acc[mt][1];
            sgate[(r0 + 8) * 32 + cb]      = acc[mt][2];
            sgate[(r0 + 8) * 32 + cb + 1]  = acc[mt][3];
        }
        __syncthreads();

        // ---- fused LSTM gate epilogue: c in registers ----
        #pragma unroll
        for (int q = 0; q < 2; q++) {
            int idx = tid + q * 256;
            int b  = idx >> 3;
            int jl = idx & 7;
            float pf = sgate[b * 32 + jl * 4 + 0] + xpv[q].x;
            float pi = sgate[b * 32 + jl * 4 + 1] + xpv[q].y;
            float po = sgate[b * 32 + jl * 4 + 2] + xpv[q].z;
            float pc = sgate[b * 32 + jl * 4 + 3] + xpv[q].w;
            float fg = 1.f / (1.f + expf(-pf));
            float ig = 1.f / (1.f + expf(-pi));
            float og = 1.f / (1.f + expf(-po));
            float ct = tanhf(pc);
            cv[q] = fg * cv[q] + ig * ct;
            float hnew = og * tanhf(cv[q]);
            __nv_bfloat16 hhi, hlo;
            split_bf16(hnew, hhi, hlo);
            size_t ho = (size_t)t * BH + (size_t)b * H_ + ej[q];
            g_Hshi[ho] = hhi;
            g_Hslo[ho] = hlo;
        }

        // ---- device-wide barrier: release step t ----
        __threadfence();
        __syncthreads();
        if (tid == 0) {
            unsigned old = atomicAdd(&g_bar_count, 1);
            if (old == (unsigned)(gridDim.x - 1)) {
                g_bar_count = 0;
                __threadfence();
                atomicExch(&g_bar_gen, (unsigned)(t + 1));
            } else {
                while (atomicAdd(&g_bar_gen, 0u) < (unsigned)(t + 1)) { }
            }
            __threadfence();
        }
        __syncthreads();
    }

    // write back cell state
    #pragma unroll
    for (int q = 0; q < 2; q++)
        g_c[eb[q] * H_ + ej[q]] = cv[q];
}

// ---------------- final h / c copy ----------------
__global__ void write_hc(float* __restrict__ dst)
{
    int i = blockIdx.x * blockDim.x + threadIdx.x;
    if (i < BH) {
        size_t o = (size_t)(T_ - 1) * BH + i;
        dst[i]      = __bfloat162float(g_Hshi[o]) + __bfloat162float(g_Hslo[o]);
        dst[BH + i] = g_c[i];
    }
}

// ---------------- launch ----------------
extern "C" void kernel_launch(void* const* d_in, const int* in_sizes, int n_in,
                              void* d_out, int out_size)
{
    const float* input_seq = (const float*)d_in[0];
    const float* hidden    = (const float*)d_in[1];
    const float* cell      = (const float*)d_in[2];
    const float* Wf        = (const float*)d_in[3];
    const float* bf        = (const float*)d_in[4];
    const float* Wi        = (const float*)d_in[5];
    const float* bi        = (const float*)d_in[6];
    const float* Wo        = (const float*)d_in[7];
    const float* bo        = (const float*)d_in[8];
    const float* Wc        = (const float*)d_in[9];
    const float* bc        = (const float*)d_in[10];
    const float* Wout      = (const float*)d_in[11];
    const float* bout      = (const float*)d_in[12];
    float* out = (float*)d_out;

    cudaFuncSetAttribute(gemm_bf16x3, cudaFuncAttributeMaxDynamicSharedMemorySize, GEMM_SMEM);
    cudaFuncSetAttribute(lstm_mma_persistent, cudaFuncAttributeMaxDynamicSharedMemorySize, REC_SMEM);

    float *pBias, *pX;
    __nv_bfloat16 *pAhi, *pAlo, *pWxh, *pWxl, *pWoh, *pWol, *pHsh, *pHsl;
    cudaGetSymbolAddress((void**)&pBias, g_bias);
    cudaGetSymbolAddress((void**)&pX,    g_Xproj);
    cudaGetSymbolAddress((void**)&pAhi,  g_Ahi);
    cudaGetSymbolAddress((void**)&pAlo,  g_Alo);
    cudaGetSymbolAddress((void**)&pWxh,  g_WxThi);
    cudaGetSymbolAddress((void**)&pWxl,  g_WxTlo);
    cudaGetSymbolAddress((void**)&pWoh,  g_WoThi);
    cudaGetSymbolAddress((void**)&pWol,  g_WoTlo);
    cudaGetSymbolAddress((void**)&pHsh,  g_Hshi);
    cudaGetSymbolAddress((void**)&pHsl,  g_Hslo);

    // 1. packs + splits
    pack_gates_t<<<48 * 32, 256>>>(Wf, Wi, Wo, Wc);
    pack_wout_t<<<32 * 8, 256>>>(Wout);
    {
        size_t n = (size_t)T_ * B_ * E_;
        split_src<<<(int)((n + 255) / 256), 256>>>(input_seq, pAhi, pAlo, n);
    }
    init_state<<<(BH + 255) / 256, 256>>>(hidden, cell, bf, bi, bo, bc);

    // 2. Xproj = A @ WxT^T + bias  (M=32768, N=4096, K=512)
    {
        dim3 grid(G4 / 128, (T_ * B_) / 64);
        gemm_bf16x3<<<grid, 128, GEMM_SMEM>>>(pAhi, pAlo, pWxh, pWxl, pBias, pX, E_, G4);
    }

    // 3. recurrence (persistent tensor-core kernel)
    lstm_mma_persistent<<<NCTA_STEP, 256, REC_SMEM>>>();

    // 4. out GEMM (M=32768, N=256, K=1024)
    {
        dim3 grid(V_ / 128, (T_ * B_) / 64);
        gemm_bf16x3<<<grid, 128, GEMM_SMEM>>>(pHsh, pHsl, pWoh, pWol, bout, out, H_, V_);
    }

    // 5. final h, c
    write_hc<<<(BH + 255) / 256, 256>>>(out + (size_t)T_ * B_ * V_);
}

// round 10
// speedup vs baseline: 6.2024x; 1.3061x over previous
#include <cuda_runtime.h>
#include <cuda_fp16.h>
#include <math.h>
#include <stdint.h>

// Problem dims
#define T_  512
#define B_  64
#define E_  512
#define H_  1024
#define V_  256
#define G4  4096   // 4*H gate-interleaved: col n = 4*j + g

#define NCTA_STEP 128
#define BH  (B_ * H_)

// ---------------- scratch (device globals; allocation-free) ----------------
__device__ float g_bias[G4];
__device__ float g_Xproj[(size_t)T_ * B_ * G4];       // 512 MB
__device__ float g_c[B_ * H_];
__device__ unsigned g_bar_count;
__device__ unsigned g_bar_gen;

// fp16 operands (16B aligned)
__device__ __align__(16) __half g_Xf16[(size_t)T_ * B_ * E_];   // input_seq fp16
__device__ __align__(16) __half g_WxThi[G4 * E_];               // WxT[n][k] hi
__device__ __align__(16) __half g_WxTlo[G4 * E_];               // WxT[n][k] lo
__device__ __align__(16) __half g_WhThi[G4 * H_];               // WhT[n][k] hi
__device__ __align__(16) __half g_WhTlo[G4 * H_];               // WhT[n][k] lo
__device__ __align__(16) __half g_WoThi[V_ * H_];               // WoT[v][k] hi
__device__ __align__(16) __half g_WoTlo[V_ * H_];               // WoT[v][k] lo
__device__ __align__(16) __half g_h0hi[BH];
__device__ __align__(16) __half g_h0lo[BH];
__device__ __align__(16) __half g_Hshi[(size_t)T_ * BH];        // h_t fp16 hi (A for t+1, out-GEMM)
__device__ __align__(16) __half g_Hslo[(size_t)T_ * BH];        // h_t fp16 lo (final-h accuracy)

// ---------------- PTX helpers (plain-sm_100 legal) ----------------
__device__ __forceinline__ uint32_t smem_u32(const void* p) {
    uint32_t a;
    asm("{ .reg .u64 t; cvta.to.shared.u64 t, %1; cvt.u32.u64 %0, t; }" : "=r"(a) : "l"(p));
    return a;
}
#define SWZ128(o) ((o) ^ (((o) >> 3) & 0x70))

#define CP16(dst, src) \
    asm volatile("cp.async.cg.shared.global [%0], [%1], 16;" :: "r"(dst), "l"(src))
#define CP_COMMIT() asm volatile("cp.async.commit_group;" ::: "memory")
#define CP_WAIT1()  asm volatile("cp.async.wait_group 1;" ::: "memory")
#define CP_WAIT0()  asm volatile("cp.async.wait_group 0;" ::: "memory")

#define LDSM4(r, addr) \
    asm volatile("ldmatrix.sync.aligned.m8n8.x4.shared.b16 {%0,%1,%2,%3}, [%4];" \
        : "=r"((r)[0]), "=r"((r)[1]), "=r"((r)[2]), "=r"((r)[3]) : "r"(addr))

#define MMAF16(c, a, b0, b1) \
    asm volatile("mma.sync.aligned.m16n8k16.row.col.f32.f16.f16.f32 " \
        "{%0,%1,%2,%3}, {%4,%5,%6,%7}, {%8,%9}, {%0,%1,%2,%3};" \
        : "+f"((c)[0]), "+f"((c)[1]), "+f"((c)[2]), "+f"((c)[3]) \
        : "r"((a)[0]), "r"((a)[1]), "r"((a)[2]), "r"((a)[3]), "r"(b0), "r"(b1))

__device__ __forceinline__ void split_f16(float v, __half& hi, __half& lo) {
    hi = __float2half_rn(v);
    lo = __float2half_rn(v - __half2float(hi));
}

// ---------------- packs: smem-tiled transposes (coalesced both sides) ----------------
__global__ __launch_bounds__(256) void pack_gates_t(
    const float* __restrict__ Wf, const float* __restrict__ Wi,
    const float* __restrict__ Wo, const float* __restrict__ Wc)
{
    __shared__ float tile[4][32][33];
    const int tid = threadIdx.x;
    const int jt  = blockIdx.x & 31;          // j tile (H/32 = 32)
    const int kt  = blockIdx.x >> 5;          // k tile ((E+H)/32 = 48)
    const int k0  = kt * 32, j0 = jt * 32;

    const float* W[4] = {Wf, Wi, Wo, Wc};
    #pragma unroll
    for (int g = 0; g < 4; g++)
        #pragma unroll
        for (int i = 0; i < 4; i++) {
            int u = tid + i * 256;
            int r = u >> 5, c = u & 31;
            tile[g][r][c] = W[g][(size_t)(k0 + r) * H_ + j0 + c];
        }
    __syncthreads();

    const bool isWx = (k0 < E_);
    const int kb = isWx ? k0 : (k0 - E_);
    const int K  = isWx ? E_ : H_;
    __half* Dh = isWx ? g_WxThi : g_WhThi;
    __half* Dl = isWx ? g_WxTlo : g_WhTlo;

    #pragma unroll
    for (int i = 0; i < 16; i++) {
        int rowu = (tid >> 5) + i * 8;        // 0..127 output rows within tile
        int g  = rowu & 3;
        int jj = rowu >> 2;
        int kk = tid & 31;
        float v = tile[g][kk][jj];
        __half hi, lo;
        split_f16(v, hi, lo);
        size_t o = (size_t)((j0 + jj) * 4 + g) * K + kb + kk;
        Dh[o] = hi;
        Dl[o] = lo;
    }
}

// Wout [H][V] row-major -> WoT[v][k]
__global__ __launch_bounds__(256) void pack_wout_t(const float* __restrict__ Wout)
{
    __shared__ float tile[32][33];
    const int tid = threadIdx.x;
    const int vt  = blockIdx.x & 7;           // V/32 = 8
    const int kt  = blockIdx.x >> 3;          // H/32 = 32
    const int k0  = kt * 32, v0 = vt * 32;

    #pragma unroll
    for (int i = 0; i < 4; i++) {
        int u = tid + i * 256;
        int r = u >> 5, c = u & 31;
        tile[r][c] = Wout[(size_t)(k0 + r) * V_ + v0 + c];
    }
    __syncthreads();

    #pragma unroll
    for (int i = 0; i < 4; i++) {
        int u = tid + i * 256;
        int vv = u >> 5, kk = u & 31;
        float val = tile[kk][vv];
        __half hi, lo;
        split_f16(val, hi, lo);
        size_t o = (size_t)(v0 + vv) * H_ + k0 + kk;
        g_WoThi[o] = hi;
        g_WoTlo[o] = lo;
    }
}

__global__ void convert_x(const float* __restrict__ src, __half* __restrict__ dst, size_t n)
{
    size_t i = (size_t)blockIdx.x * blockDim.x + threadIdx.x;
    if (i < n) dst[i] = __float2half_rn(src[i]);
}

// ---------------- init state (+ bias pack) ----------------
__global__ void init_state(const float* __restrict__ hidden, const float* __restrict__ cell,
                           const float* __restrict__ bf, const float* __restrict__ bi,
                           const float* __restrict__ bo, const float* __restrict__ bc)
{
    int i = blockIdx.x * blockDim.x + threadIdx.x;
    if (i < BH) {
        __half hi, lo;
        split_f16(hidden[i], hi, lo);
        g_h0hi[i] = hi;
        g_h0lo[i] = lo;
        g_c[i]    = cell[i];
    }
    if (i < H_) {
        g_bias[i * 4 + 0] = bf[i];
        g_bias[i * 4 + 1] = bi[i];
        g_bias[i * 4 + 2] = bo[i];
        g_bias[i * 4 + 3] = bc[i];
    }
    if (i == 0) { g_bar_count = 0; g_bar_gen = 0; }
}

// ---------------- fp16 2-term GEMM: C = A@Bhi^T + A@Blo^T + bias ----------------
// A: M x K fp16 (K-contig rows); B: N x K fp16 hi/lo. CTA tile 64x128, 4 warps.
#define STG2        40960     // A 8K | Bhi 16K | Blo 16K
#define O2_A        0
#define O2_BHI      8192
#define O2_BLO      24576
#define GEMM_SMEM   (2 * STG2)

__device__ __forceinline__ void stage_fill2(
    uint32_t sstage, const __half* __restrict__ A,
    const __half* __restrict__ Bhi, const __half* __restrict__ Blo,
    int m0, int n0, int kc, int K, int tid)
{
    #pragma unroll
    for (int i = 0; i < 4; i++) {             // A: 64 rows x 8 cu
        int u  = tid + i * 128;
        int r  = u >> 3;
        int cu = u & 7;
        uint32_t dsw = SWZ128((uint32_t)(r * 128 + cu * 16));
        CP16(sstage + O2_A + dsw, A + (size_t)(m0 + r) * K + kc + cu * 8);
    }
    #pragma unroll
    for (int i = 0; i < 8; i++) {             // B: 128 rows x 8 cu
        int u  = tid + i * 128;
        int r  = u >> 3;
        int cu = u & 7;
        uint32_t dsw = SWZ128((uint32_t)(r * 128 + cu * 16));
        size_t bo = (size_t)(n0 + r) * K + kc + cu * 8;
        CP16(sstage + O2_BHI + dsw, Bhi + bo);
        CP16(sstage + O2_BLO + dsw, Blo + bo);
    }
}

__global__ __launch_bounds__(128, 2) void gemm_f16_2t(
    const __half* __restrict__ A,
    const __half* __restrict__ Bhi, const __half* __restrict__ Blo,
    const float* __restrict__ bias, float* __restrict__ C,
    int K, int ldc)
{
    extern __shared__ char smem[];
    const uint32_t sbase = smem_u32(smem);
    const int tid  = threadIdx.x;
    const int lane = tid & 31;
    const int w    = tid >> 5;
    const int wm   = w & 1;          // m offset wm*32
    const int wn   = w >> 1;         // n offset wn*64
    const int m0 = blockIdx.y * 64;
    const int n0 = blockIdx.x * 128;
    const int NC = K / 64;

    float acc[2][8][4];
    #pragma unroll
    for (int mt = 0; mt < 2; mt++)
        #pragma unroll
        for (int nt = 0; nt < 8; nt++)
            #pragma unroll
            for (int q = 0; q < 4; q++) acc[mt][nt][q] = 0.f;

    stage_fill2(sbase, A, Bhi, Blo, m0, n0, 0, K, tid);
    CP_COMMIT();

    const int a_row = (lane & 15);
    const int a_cuh = (lane >> 4);
    const int b_row = (lane & 7) + ((lane >> 4) << 3);
    const int b_cuh = ((lane >> 3) & 1);

    #pragma unroll 1
    for (int c = 0; c < NC; c++) {
        if (c + 1 < NC) {
            stage_fill2(sbase + ((c + 1) & 1) * STG2, A, Bhi, Blo,
                        m0, n0, (c + 1) * 64, K, tid);
            CP_COMMIT();
            CP_WAIT1();
        } else {
            CP_WAIT0();
        }
        __syncthreads();

        const uint32_t sS = sbase + (c & 1) * STG2;

        #pragma unroll
        for (int ks = 0; ks < 4; ks++) {
            uint32_t aF[2][4], bH[4][4], bL[4][4];
            #pragma unroll
            for (int mt = 0; mt < 2; mt++) {
                int row = wm * 32 + mt * 16 + a_row;
                int cu  = ks * 2 + a_cuh;
                uint32_t off = SWZ128((uint32_t)(row * 128 + cu * 16));
                LDSM4(aF[mt], sS + O2_A + off);
            }
            #pragma unroll
            for (int np = 0; np < 4; np++) {
                int row = wn * 64 + np * 16 + b_row;
                int cu  = ks * 2 + b_cuh;
                uint32_t off = SWZ128((uint32_t)(row * 128 + cu * 16));
                LDSM4(bH[np], sS + O2_BHI + off);
                LDSM4(bL[np], sS + O2_BLO + off);
            }
            #pragma unroll
            for (int mt = 0; mt < 2; mt++)
                #pragma unroll
                for (int np = 0; np < 4; np++) {
                    MMAF16(acc[mt][2 * np],     aF[mt], bH[np][0], bH[np][1]);
                    MMAF16(acc[mt][2 * np + 1], aF[mt], bH[np][2], bH[np][3]);
                    MMAF16(acc[mt][2 * np],     aF[mt], bL[np][0], bL[np][1]);
                    MMAF16(acc[mt][2 * np + 1], aF[mt], bL[np][2], bL[np][3]);
                }
        }
        __syncthreads();
    }

    #pragma unroll
    for (int mt = 0; mt < 2; mt++) {
        int rbase = m0 + wm * 32 + mt * 16 + (lane >> 2);
        #pragma unroll
        for (int nt = 0; nt < 8; nt++) {
            int col = n0 + wn * 64 + nt * 8 + (lane & 3) * 2;
            float2 bv = *(const float2*)&bias[col];
            float2 v0, v1;
            v0.x = acc[mt][nt][0] + bv.x;
            v0.y = acc[mt][nt][1] + bv.y;
            v1.x = acc[mt][nt][2] + bv.x;
            v1.y = acc[mt][nt][3] + bv.y;
            *(float2*)&C[(size_t)rbase * ldc + col]       = v0;
            *(float2*)&C[(size_t)(rbase + 8) * ldc + col] = v1;
        }
    }
}

// ---------------- persistent tensor-core LSTM recurrence ----------------
// 128 CTAs x 256 threads. CTA owns 32 gate-cols. Wh tile RESIDENT in smem
// (128 KB, loaded once). Per step only h (fp16, 128 KB CTA-read) streams.
// 2-term fp16 MMA with separate accumulators. c in registers.
#define RB_HI       0                    // 64 KB  Wh hi: 16 blocks of 32x64
#define RB_LO       65536                // 64 KB  Wh lo
#define RA_BASE     131072               // 2 x 16 KB A stages (each: two 8 KB k64 sub-blocks)
#define R_SGATE     163840               // 8 KB fp32 [64][32]
#define REC_SMEM    172032

__global__ __launch_bounds__(256, 1) void lstm_mma_persistent()
{
    extern __shared__ char smem[];
    const uint32_t sbase = smem_u32(smem);
    float* sgate = (float*)(smem + R_SGATE);

    const int tid  = threadIdx.x;
    const int lane = tid & 31;
    const int w    = tid >> 5;
    const int wm   = w & 1;          // m offset wm*32
    const int wn   = w >> 1;         // n offset wn*8
    const int n0   = blockIdx.x * 32;

    const int a_row = (lane & 15);
    const int a_cuh = (lane >> 4);
    const int b_row = (lane & 7);
    const int b_cu4 = ((lane >> 3) & 3);

    // ---- load resident Wh tile (once) ----
    #pragma unroll
    for (int i = 0; i < 16; i++) {
        int u   = tid + i * 256;          // 0..4095
        int blk = u >> 8;                 // k64 block 0..15
        int rem = u & 255;
        int r   = rem >> 3, cu = rem & 7;
        uint32_t dsw = (uint32_t)(blk * 4096) + SWZ128((uint32_t)(r * 128 + cu * 16));
        size_t src = (size_t)(n0 + r) * H_ + blk * 64 + cu * 8;
        CP16(sbase + RB_HI + dsw, g_WhThi + src);
        CP16(sbase + RB_LO + dsw, g_WhTlo + src);
    }
    CP_COMMIT();
    CP_WAIT0();
    __syncthreads();

    // epilogue ownership (fixed across steps): idx q -> (b, j)
    int eb[2], ej[2];
    float cv[2];
    #pragma unroll
    for (int q = 0; q < 2; q++) {
        int idx = tid + q * 256;
        eb[q] = idx >> 3;
        ej[q] = (n0 >> 2) + (idx & 7);
        cv[q] = g_c[eb[q] * H_ + ej[q]];
    }

    for (int t = 0; t < T_; t++) {
        const __half* A_t = (t == 0) ? g_h0hi : g_Hshi + (size_t)(t - 1) * BH;
        const float* xp_t = g_Xproj + (size_t)t * B_ * G4;

        // prefetch per-step epilogue operands (hidden under mainloop)
        float4 xpv[2];
        #pragma unroll
        for (int q = 0; q < 2; q++) {
            int jl = (tid + q * 256) & 7;
            xpv[q] = *(const float4*)&xp_t[(size_t)eb[q] * G4 + n0 + jl * 4];
        }

        float accH[2][4], accL[2][4];
        #pragma unroll
        for (int mt = 0; mt < 2; mt++)
            #pragma unroll
            for (int q = 0; q < 4; q++) { accH[mt][q] = 0.f; accL[mt][q] = 0.f; }

        // ---- prologue: fill A chunk 0 (k128 = 16 KB) ----
        #pragma unroll
        for (int i = 0; i < 4; i++) {
            int u = tid + i * 256;            // 0..1023
            int s = u >> 9;
            int rem = u & 511;
            int r = rem >> 3, cu = rem & 7;
            uint32_t dsw = (uint32_t)(s * 8192) + SWZ128((uint32_t)(r * 128 + cu * 16));
            CP16(sbase + RA_BASE + dsw, A_t + (size_t)r * H_ + s * 64 + cu * 8);
        }
        CP_COMMIT();

        #pragma unroll 1
        for (int c = 0; c < H_ / 128; c++) {
            if (c + 1 < H_ / 128) {
                uint32_t sN = sbase + RA_BASE + ((c + 1) & 1) * 16384;
                int kc = (c + 1) * 128;
                #pragma unroll
                for (int i = 0; i < 4; i++) {
                    int u = tid + i * 256;
                    int s = u >> 9;
                    int rem = u & 511;
                    int r = rem >> 3, cu = rem & 7;
                    uint32_t dsw = (uint32_t)(s * 8192) + SWZ128((uint32_t)(r * 128 + cu * 16));
                    CP16(sN + dsw, A_t + (size_t)r * H_ + kc + s * 64 + cu * 8);
                }
                CP_COMMIT();
                CP_WAIT1();
            } else {
                CP_WAIT0();
            }
            __syncthreads();

            const uint32_t sA = sbase + RA_BASE + (c & 1) * 16384;

            #pragma unroll
            for (int s = 0; s < 2; s++) {
                const int blk = c * 2 + s;
                const uint32_t bHb = sbase + RB_HI + blk * 4096;
                const uint32_t bLb = sbase + RB_LO + blk * 4096;
                const uint32_t aB  = sA + s * 8192;

                #pragma unroll
                for (int ks2 = 0; ks2 < 2; ks2++) {
                    uint32_t bH[4], bL[4];
                    {
                        int row = wn * 8 + b_row;
                        int cu  = ks2 * 4 + b_cu4;
                        uint32_t off = SWZ128((uint32_t)(row * 128 + cu * 16));
                        LDSM4(bH, bHb + off);
                        LDSM4(bL, bLb + off);
                    }
                    #pragma unroll
                    for (int ks = 0; ks < 2; ks++) {
                        uint32_t aF[2][4];
                        #pragma unroll
                        for (int mt = 0; mt < 2; mt++) {
                            int row = wm * 32 + mt * 16 + a_row;
                            int cu  = ks2 * 4 + ks * 2 + a_cuh;
                            uint32_t off = SWZ128((uint32_t)(row * 128 + cu * 16));
                            LDSM4(aF[mt], aB + off);
                        }
                        #pragma unroll
                        for (int mt = 0; mt < 2; mt++) {
                            MMAF16(accH[mt], aF[mt], bH[2 * ks], bH[2 * ks + 1]);
                            MMAF16(accL[mt], aF[mt], bL[2 * ks], bL[2 * ks + 1]);
                        }
                    }
                }
            }
            __syncthreads();
        }

        // ---- stage preacts to smem so each thread gathers a full gate quad ----
        #pragma unroll
        for (int mt = 0; mt < 2; mt++) {
            int r0 = wm * 32 + mt * 16 + (lane >> 2);
            int cb = wn * 8 + (lane & 3) * 2;
            sgate[r0 * 32 + cb]            = accH[mt][0] + accL[mt][0];
            sgate[r0 * 32 + cb + 1]        = accH[mt][1] + accL[mt][1];
            sgate[(r0 + 8) * 32 + cb]      = accH[mt][2] + accL[mt][2];
            sgate[(r0 + 8) * 32 + cb + 1]  = accH[mt][3] + accL[mt][3];
        }
        __syncthreads();

        // ---- fused LSTM gate epilogue: c in registers ----
        #pragma unroll
        for (int q = 0; q < 2; q++) {
            int idx = tid + q * 256;
            int b  = idx >> 3;
            int jl = idx & 7;
            float pf = sgate[b * 32 + jl * 4 + 0] + xpv[q].x;
            float pi = sgate[b * 32 + jl * 4 + 1] + xpv[q].y;
            float po = sgate[b * 32 + jl * 4 + 2] + xpv[q].z;
            float pc = sgate[b * 32 + jl * 4 + 3] + xpv[q].w;
            float fg = 1.f / (1.f + expf(-pf));
            float ig = 1.f / (1.f + expf(-pi));
            float og = 1.f / (1.f + expf(-po));
            float ct = tanhf(pc);
            cv[q] = fg * cv[q] + ig * ct;
            float hnew = og * tanhf(cv[q]);
            __half hhi, hlo;
            split_f16(hnew, hhi, hlo);
            size_t ho = (size_t)t * BH + (size_t)b * H_ + ej[q];
            g_Hshi[ho] = hhi;
            g_Hslo[ho] = hlo;
        }

        // ---- device-wide barrier: release step t ----
        __threadfence();
        __syncthreads();
        if (tid == 0) {
            unsigned old = atomicAdd(&g_bar_count, 1);
            if (old == (unsigned)(gridDim.x - 1)) {
                g_bar_count = 0;
                __threadfence();
                atomicExch(&g_bar_gen, (unsigned)(t + 1));
            } else {
                while (atomicAdd(&g_bar_gen, 0u) < (unsigned)(t + 1)) { }
            }
            __threadfence();
        }
        __syncthreads();
    }

    // write back cell state
    #pragma unroll
    for (int q = 0; q < 2; q++)
        g_c[eb[q] * H_ + ej[q]] = cv[q];
}

// ---------------- final h / c copy (hi+lo reconstruction) ----------------
__global__ void write_hc(float* __restrict__ dst)
{
    int i = blockIdx.x * blockDim.x + threadIdx.x;
    if (i < BH) {
        size_t o = (size_t)(T_ - 1) * BH + i;
        dst[i]      = __half2float(g_Hshi[o]) + __half2float(g_Hslo[o]);
        dst[BH + i] = g_c[i];
    }
}

// ---------------- launch ----------------
extern "C" void kernel_launch(void* const* d_in, const int* in_sizes, int n_in,
                              void* d_out, int out_size)
{
    const float* input_seq = (const float*)d_in[0];
    const float* hidden    = (const float*)d_in[1];
    const float* cell      = (const float*)d_in[2];
    const float* Wf        = (const float*)d_in[3];
    const float* bf        = (const float*)d_in[4];
    const float* Wi        = (const float*)d_in[5];
    const float* bi        = (const float*)d_in[6];
    const float* Wo        = (const float*)d_in[7];
    const float* bo        = (const float*)d_in[8];
    const float* Wc        = (const float*)d_in[9];
    const float* bc        = (const float*)d_in[10];
    const float* Wout      = (const float*)d_in[11];
    const float* bout      = (const float*)d_in[12];
    float* out = (float*)d_out;

    cudaFuncSetAttribute(gemm_f16_2t, cudaFuncAttributeMaxDynamicSharedMemorySize, GEMM_SMEM);
    cudaFuncSetAttribute(lstm_mma_persistent, cudaFuncAttributeMaxDynamicSharedMemorySize, REC_SMEM);

    float *pBias, *pX;
    __half *pXf, *pWxh, *pWxl, *pWoh, *pWol, *pHsh;
    cudaGetSymbolAddress((void**)&pBias, g_bias);
    cudaGetSymbolAddress((void**)&pX,    g_Xproj);
    cudaGetSymbolAddress((void**)&pXf,   g_Xf16);
    cudaGetSymbolAddress((void**)&pWxh,  g_WxThi);
    cudaGetSymbolAddress((void**)&pWxl,  g_WxTlo);
    cudaGetSymbolAddress((void**)&pWoh,  g_WoThi);
    cudaGetSymbolAddress((void**)&pWol,  g_WoTlo);
    cudaGetSymbolAddress((void**)&pHsh,  g_Hshi);

    // 1. packs + conversions
    pack_gates_t<<<48 * 32, 256>>>(Wf, Wi, Wo, Wc);
    pack_wout_t<<<32 * 8, 256>>>(Wout);
    {
        size_t n = (size_t)T_ * B_ * E_;
        convert_x<<<(int)((n + 255) / 256), 256>>>(input_seq, pXf, n);
    }
    init_state<<<(BH + 255) / 256, 256>>>(hidden, cell, bf, bi, bo, bc);

    // 2. Xproj = X @ WxT^T + bias  (M=32768, N=4096, K=512), fp16 2-term
    {
        dim3 grid(G4 / 128, (T_ * B_) / 64);
        gemm_f16_2t<<<grid, 128, GEMM_SMEM>>>(pXf, pWxh, pWxl, pBias, pX, E_, G4);
    }

    // 3. recurrence (persistent tensor-core kernel, Wh smem-resident)
    lstm_mma_persistent<<<NCTA_STEP, 256, REC_SMEM>>>();

    // 4. out GEMM (M=32768, N=256, K=1024), fp16 2-term
    {
        dim3 grid(V_ / 128, (T_ * B_) / 64);
        gemm_f16_2t<<<grid, 128, GEMM_SMEM>>>(pHsh, pWoh, pWol, bout, out, H_, V_);
    }

    // 5. final h, c
    write_hc<<<(BH + 255) / 256, 256>>>(out + (size_t)T_ * B_ * V_);
}

// round 11
// speedup vs baseline: 6.2456x; 1.0070x over previous
#include <cuda_runtime.h>
#include <cuda_fp16.h>
#include <math.h>
#include <stdint.h>

// Problem dims
#define T_  512
#define B_  64
#define E_  512
#define H_  1024
#define V_  256
#define G4  4096   // 4*H gate-interleaved: col n = 4*j + g

#define NCTA_STEP 128
#define BH  (B_ * H_)

// ---------------- scratch (device globals; allocation-free) ----------------
__device__ float g_bias[G4];
__device__ float g_Xproj[(size_t)T_ * B_ * G4];       // 512 MB
__device__ float g_c[B_ * H_];
__device__ unsigned g_bar_count;
__device__ unsigned g_bar_gen;

// fp16 operands (16B aligned)
__device__ __align__(16) __half g_Xf16[(size_t)T_ * B_ * E_];   // input_seq fp16
__device__ __align__(16) __half g_WxThi[G4 * E_];               // WxT[n][k] hi
__device__ __align__(16) __half g_WxTlo[G4 * E_];               // WxT[n][k] lo
__device__ __align__(16) __half g_WhThi[G4 * H_];               // WhT[n][k] hi
__device__ __align__(16) __half g_WhTlo[G4 * H_];               // WhT[n][k] lo
__device__ __align__(16) __half g_WoThi[V_ * H_];               // WoT[v][k] hi
__device__ __align__(16) __half g_WoTlo[V_ * H_];               // WoT[v][k] lo
__device__ __align__(16) __half g_h0hi[BH];
__device__ __align__(16) __half g_h0lo[BH];
__device__ __align__(16) __half g_Hshi[(size_t)T_ * BH];        // h_t fp16 hi (A for t+1, out-GEMM)
__device__ __align__(16) __half g_Hslo[(size_t)T_ * BH];        // h_t fp16 lo (final-h accuracy)

// ---------------- PTX helpers (plain-sm_100 legal) ----------------
__device__ __forceinline__ uint32_t smem_u32(const void* p) {
    uint32_t a;
    asm("{ .reg .u64 t; cvta.to.shared.u64 t, %1; cvt.u32.u64 %0, t; }" : "=r"(a) : "l"(p));
    return a;
}
#define SWZ128(o) ((o) ^ (((o) >> 3) & 0x70))

#define CP16(dst, src) \
    asm volatile("cp.async.cg.shared.global [%0], [%1], 16;" :: "r"(dst), "l"(src))
#define CP_COMMIT() asm volatile("cp.async.commit_group;" ::: "memory")
#define CP_WAIT1()  asm volatile("cp.async.wait_group 1;" ::: "memory")
#define CP_WAIT0()  asm volatile("cp.async.wait_group 0;" ::: "memory")

#define LDSM4(r, addr) \
    asm volatile("ldmatrix.sync.aligned.m8n8.x4.shared.b16 {%0,%1,%2,%3}, [%4];" \
        : "=r"((r)[0]), "=r"((r)[1]), "=r"((r)[2]), "=r"((r)[3]) : "r"(addr))

#define MMAF16(c, a, b0, b1) \
    asm volatile("mma.sync.aligned.m16n8k16.row.col.f32.f16.f16.f32 " \
        "{%0,%1,%2,%3}, {%4,%5,%6,%7}, {%8,%9}, {%0,%1,%2,%3};" \
        : "+f"((c)[0]), "+f"((c)[1]), "+f"((c)[2]), "+f"((c)[3]) \
        : "r"((a)[0]), "r"((a)[1]), "r"((a)[2]), "r"((a)[3]), "r"(b0), "r"(b1))

__device__ __forceinline__ void split_f16(float v, __half& hi, __half& lo) {
    hi = __float2half_rn(v);
    lo = __float2half_rn(v - __half2float(hi));
}

// ---------------- packs: smem-tiled transposes (coalesced both sides) ----------------
__global__ __launch_bounds__(256) void pack_gates_t(
    const float* __restrict__ Wf, const float* __restrict__ Wi,
    const float* __restrict__ Wo, const float* __restrict__ Wc)
{
    __shared__ float tile[4][32][33];
    const int tid = threadIdx.x;
    const int jt  = blockIdx.x & 31;          // j tile (H/32 = 32)
    const int kt  = blockIdx.x >> 5;          // k tile ((E+H)/32 = 48)
    const int k0  = kt * 32, j0 = jt * 32;

    const float* W[4] = {Wf, Wi, Wo, Wc};
    #pragma unroll
    for (int g = 0; g < 4; g++)
        #pragma unroll
        for (int i = 0; i < 4; i++) {
            int u = tid + i * 256;
            int r = u >> 5, c = u & 31;
            tile[g][r][c] = W[g][(size_t)(k0 + r) * H_ + j0 + c];
        }
    __syncthreads();

    const bool isWx = (k0 < E_);
    const int kb = isWx ? k0 : (k0 - E_);
    const int K  = isWx ? E_ : H_;
    __half* Dh = isWx ? g_WxThi : g_WhThi;
    __half* Dl = isWx ? g_WxTlo : g_WhTlo;

    #pragma unroll
    for (int i = 0; i < 16; i++) {
        int rowu = (tid >> 5) + i * 8;        // 0..127 output rows within tile
        int g  = rowu & 3;
        int jj = rowu >> 2;
        int kk = tid & 31;
        float v = tile[g][kk][jj];
        __half hi, lo;
        split_f16(v, hi, lo);
        size_t o = (size_t)((j0 + jj) * 4 + g) * K + kb + kk;
        Dh[o] = hi;
        Dl[o] = lo;
    }
}

// Wout [H][V] row-major -> WoT[v][k]
__global__ __launch_bounds__(256) void pack_wout_t(const float* __restrict__ Wout)
{
    __shared__ float tile[32][33];
    const int tid = threadIdx.x;
    const int vt  = blockIdx.x & 7;           // V/32 = 8
    const int kt  = blockIdx.x >> 3;          // H/32 = 32
    const int k0  = kt * 32, v0 = vt * 32;

    #pragma unroll
    for (int i = 0; i < 4; i++) {
        int u = tid + i * 256;
        int r = u >> 5, c = u & 31;
        tile[r][c] = Wout[(size_t)(k0 + r) * V_ + v0 + c];
    }
    __syncthreads();

    #pragma unroll
    for (int i = 0; i < 4; i++) {
        int u = tid + i * 256;
        int vv = u >> 5, kk = u & 31;
        float val = tile[kk][vv];
        __half hi, lo;
        split_f16(val, hi, lo);
        size_t o = (size_t)(v0 + vv) * H_ + k0 + kk;
        g_WoThi[o] = hi;
        g_WoTlo[o] = lo;
    }
}

__global__ void convert_x(const float* __restrict__ src, __half* __restrict__ dst, size_t n)
{
    size_t i = (size_t)blockIdx.x * blockDim.x + threadIdx.x;
    if (i < n) dst[i] = __float2half_rn(src[i]);
}

// ---------------- init state (+ bias pack) ----------------
__global__ void init_state(const float* __restrict__ hidden, const float* __restrict__ cell,
                           const float* __restrict__ bf, const float* __restrict__ bi,
                           const float* __restrict__ bo, const float* __restrict__ bc)
{
    int i = blockIdx.x * blockDim.x + threadIdx.x;
    if (i < BH) {
        __half hi, lo;
        split_f16(hidden[i], hi, lo);
        g_h0hi[i] = hi;
        g_h0lo[i] = lo;
        g_c[i]    = cell[i];
    }
    if (i < H_) {
        g_bias[i * 4 + 0] = bf[i];
        g_bias[i * 4 + 1] = bi[i];
        g_bias[i * 4 + 2] = bo[i];
        g_bias[i * 4 + 3] = bc[i];
    }
    if (i == 0) { g_bar_count = 0; g_bar_gen = 0; }
}

// ---------------- fp16 2-term GEMM: C = A@Bhi^T + A@Blo^T + bias ----------------
// A: M x K fp16; B: N x K fp16 hi/lo. CTA tile 128x128, 8 warps (4m x 2n),
// 96 KB smem double-buffered -> 2 CTAs/SM. B fragments in np-halves (reg relief).
#define STG2        49152     // A 16K | Bhi 16K | Blo 16K
#define O2_A        0
#define O2_BHI      16384
#define O2_BLO      32768
#define GEMM_SMEM   (2 * STG2)

__device__ __forceinline__ void stage_fill2(
    uint32_t sstage, const __half* __restrict__ A,
    const __half* __restrict__ Bhi, const __half* __restrict__ Blo,
    int m0, int n0, int kc, int K, int tid)
{
    #pragma unroll
    for (int i = 0; i < 4; i++) {             // A: 128 rows x 8 cu
        int u  = tid + i * 256;
        int r  = u >> 3;
        int cu = u & 7;
        uint32_t dsw = SWZ128((uint32_t)(r * 128 + cu * 16));
        CP16(sstage + O2_A + dsw, A + (size_t)(m0 + r) * K + kc + cu * 8);
    }
    #pragma unroll
    for (int i = 0; i < 4; i++) {             // B: 128 rows x 8 cu
        int u  = tid + i * 256;
        int r  = u >> 3;
        int cu = u & 7;
        uint32_t dsw = SWZ128((uint32_t)(r * 128 + cu * 16));
        size_t bo = (size_t)(n0 + r) * K + kc + cu * 8;
        CP16(sstage + O2_BHI + dsw, Bhi + bo);
        CP16(sstage + O2_BLO + dsw, Blo + bo);
    }
}

__global__ __launch_bounds__(256, 2) void gemm_f16_2t(
    const __half* __restrict__ A,
    const __half* __restrict__ Bhi, const __half* __restrict__ Blo,
    const float* __restrict__ bias, float* __restrict__ C,
    int K, int ldc)
{
    extern __shared__ char smem[];
    const uint32_t sbase = smem_u32(smem);
    const int tid  = threadIdx.x;
    const int lane = tid & 31;
    const int w    = tid >> 5;
    const int wm   = w & 3;          // m offset wm*32
    const int wn   = w >> 2;         // n offset wn*64
    const int m0 = blockIdx.y * 128;
    const int n0 = blockIdx.x * 128;
    const int NC = K / 64;

    float acc[2][8][4];
    #pragma unroll
    for (int mt = 0; mt < 2; mt++)
        #pragma unroll
        for (int nt = 0; nt < 8; nt++)
            #pragma unroll
            for (int q = 0; q < 4; q++) acc[mt][nt][q] = 0.f;

    stage_fill2(sbase, A, Bhi, Blo, m0, n0, 0, K, tid);
    CP_COMMIT();

    const int a_row = (lane & 15);
    const int a_cuh = (lane >> 4);
    const int b_row = (lane & 7) + ((lane >> 4) << 3);
    const int b_cuh = ((lane >> 3) & 1);

    #pragma unroll 1
    for (int c = 0; c < NC; c++) {
        if (c + 1 < NC) {
            stage_fill2(sbase + ((c + 1) & 1) * STG2, A, Bhi, Blo,
                        m0, n0, (c + 1) * 64, K, tid);
            CP_COMMIT();
            CP_WAIT1();
        } else {
            CP_WAIT0();
        }
        __syncthreads();

        const uint32_t sS = sbase + (c & 1) * STG2;

        #pragma unroll
        for (int ks = 0; ks < 4; ks++) {
            uint32_t aF[2][4];
            #pragma unroll
            for (int mt = 0; mt < 2; mt++) {
                int row = wm * 32 + mt * 16 + a_row;
                int cu  = ks * 2 + a_cuh;
                uint32_t off = SWZ128((uint32_t)(row * 128 + cu * 16));
                LDSM4(aF[mt], sS + O2_A + off);
            }
            #pragma unroll
            for (int nh = 0; nh < 2; nh++) {          // np halves: regs stay ~110
                uint32_t bH[2][4], bL[2][4];
                #pragma unroll
                for (int p = 0; p < 2; p++) {
                    int np = nh * 2 + p;
                    int row = wn * 64 + np * 16 + b_row;
                    int cu  = ks * 2 + b_cuh;
                    uint32_t off = SWZ128((uint32_t)(row * 128 + cu * 16));
                    LDSM4(bH[p], sS + O2_BHI + off);
                    LDSM4(bL[p], sS + O2_BLO + off);
                }
                #pragma unroll
                for (int mt = 0; mt < 2; mt++)
                    #pragma unroll
                    for (int p = 0; p < 2; p++) {
                        int np = nh * 2 + p;
                        MMAF16(acc[mt][2 * np],     aF[mt], bH[p][0], bH[p][1]);
                        MMAF16(acc[mt][2 * np + 1], aF[mt], bH[p][2], bH[p][3]);
                        MMAF16(acc[mt][2 * np],     aF[mt], bL[p][0], bL[p][1]);
                        MMAF16(acc[mt][2 * np + 1], aF[mt], bL[p][2], bL[p][3]);
                    }
            }
        }
        __syncthreads();
    }

    #pragma unroll
    for (int mt = 0; mt < 2; mt++) {
        int rbase = m0 + wm * 32 + mt * 16 + (lane >> 2);
        #pragma unroll
        for (int nt = 0; nt < 8; nt++) {
            int col = n0 + wn * 64 + nt * 8 + (lane & 3) * 2;
            float2 bv = *(const float2*)&bias[col];
            float2 v0, v1;
            v0.x = acc[mt][nt][0] + bv.x;
            v0.y = acc[mt][nt][1] + bv.y;
            v1.x = acc[mt][nt][2] + bv.x;
            v1.y = acc[mt][nt][3] + bv.y;
            *(float2*)&C[(size_t)rbase * ldc + col]       = v0;
            *(float2*)&C[(size_t)(rbase + 8) * ldc + col] = v1;
        }
    }
}

// ---------------- persistent tensor-core LSTM recurrence ----------------
// 128 CTAs x 256 threads. CTA owns 32 gate-cols. Wh resident in smem (128 KB).
// Epilogue uses shfl_xor(lane^1) gate-quad exchange: no smem staging, no extra syncs.
#define RB_HI       0                    // 64 KB  Wh hi: 16 blocks of 32x64
#define RB_LO       65536                // 64 KB  Wh lo
#define RA_BASE     131072               // 2 x 16 KB A stages
#define REC_SMEM    163840

__global__ __launch_bounds__(256, 1) void lstm_mma_persistent()
{
    extern __shared__ char smem[];
    const uint32_t sbase = smem_u32(smem);

    const int tid  = threadIdx.x;
    const int lane = tid & 31;
    const int w    = tid >> 5;
    const int wm   = w & 1;          // m offset wm*32
    const int wn   = w >> 1;         // n offset wn*8
    const int n0   = blockIdx.x * 32;

    const int a_row = (lane & 15);
    const int a_cuh = (lane >> 4);
    const int b_row = (lane & 7);
    const int b_cu4 = ((lane >> 3) & 3);

    // ---- load resident Wh tile (once) ----
    #pragma unroll
    for (int i = 0; i < 16; i++) {
        int u   = tid + i * 256;          // 0..4095
        int blk = u >> 8;                 // k64 block 0..15
        int rem = u & 255;
        int r   = rem >> 3, cu = rem & 7;
        uint32_t dsw = (uint32_t)(blk * 4096) + SWZ128((uint32_t)(r * 128 + cu * 16));
        size_t src = (size_t)(n0 + r) * H_ + blk * 64 + cu * 8;
        CP16(sbase + RB_HI + dsw, g_WhThi + src);
        CP16(sbase + RB_LO + dsw, g_WhTlo + src);
    }
    CP_COMMIT();
    CP_WAIT0();
    __syncthreads();

    // epilogue ownership (fixed across steps): per mt one (b, j) pair
    const int odd = lane & 1;
    const int ju  = (n0 >> 2) + wn * 2 + ((lane & 3) >> 1);   // hidden unit
    int eb[2];
    float cv[2];
    #pragma unroll
    for (int mt = 0; mt < 2; mt++) {
        eb[mt] = wm * 32 + mt * 16 + (lane >> 2) + (odd ? 8 : 0);
        cv[mt] = g_c[eb[mt] * H_ + ju];
    }

    for (int t = 0; t < T_; t++) {
        const __half* A_t = (t == 0) ? g_h0hi : g_Hshi + (size_t)(t - 1) * BH;
        const float* xp_t = g_Xproj + (size_t)t * B_ * G4;

        // prefetch per-step epilogue operands (hidden under mainloop)
        float4 xpv[2];
        #pragma unroll
        for (int mt = 0; mt < 2; mt++)
            xpv[mt] = *(const float4*)&xp_t[(size_t)eb[mt] * G4 + ju * 4];

        float accH[2][4], accL[2][4];
        #pragma unroll
        for (int mt = 0; mt < 2; mt++)
            #pragma unroll
            for (int q = 0; q < 4; q++) { accH[mt][q] = 0.f; accL[mt][q] = 0.f; }

        // ---- prologue: fill A chunk 0 (k128 = 16 KB) ----
        #pragma unroll
        for (int i = 0; i < 4; i++) {
            int u = tid + i * 256;            // 0..1023
            int s = u >> 9;
            int rem = u & 511;
            int r = rem >> 3, cu = rem & 7;
            uint32_t dsw = (uint32_t)(s * 8192) + SWZ128((uint32_t)(r * 128 + cu * 16));
            CP16(sbase + RA_BASE + dsw, A_t + (size_t)r * H_ + s * 64 + cu * 8);
        }
        CP_COMMIT();

        #pragma unroll 1
        for (int c = 0; c < H_ / 128; c++) {
            if (c + 1 < H_ / 128) {
                uint32_t sN = sbase + RA_BASE + ((c + 1) & 1) * 16384;
                int kc = (c + 1) * 128;
                #pragma unroll
                for (int i = 0; i < 4; i++) {
                    int u = tid + i * 256;
                    int s = u >> 9;
                    int rem = u & 511;
                    int r = rem >> 3, cu = rem & 7;
                    uint32_t dsw = (uint32_t)(s * 8192) + SWZ128((uint32_t)(r * 128 + cu * 16));
                    CP16(sN + dsw, A_t + (size_t)r * H_ + kc + s * 64 + cu * 8);
                }
                CP_COMMIT();
                CP_WAIT1();
            } else {
                CP_WAIT0();
            }
            __syncthreads();

            const uint32_t sA = sbase + RA_BASE + (c & 1) * 16384;

            #pragma unroll
            for (int s = 0; s < 2; s++) {
                const int blk = c * 2 + s;
                const uint32_t bHb = sbase + RB_HI + blk * 4096;
                const uint32_t bLb = sbase + RB_LO + blk * 4096;
                const uint32_t aB  = sA + s * 8192;

                #pragma unroll
                for (int ks2 = 0; ks2 < 2; ks2++) {
                    uint32_t bH[4], bL[4];
                    {
                        int row = wn * 8 + b_row;
                        int cu  = ks2 * 4 + b_cu4;
                        uint32_t off = SWZ128((uint32_t)(row * 128 + cu * 16));
                        LDSM4(bH, bHb + off);
                        LDSM4(bL, bLb + off);
                    }
                    #pragma unroll
                    for (int ks = 0; ks < 2; ks++) {
                        uint32_t aF[2][4];
                        #pragma unroll
                        for (int mt = 0; mt < 2; mt++) {
                            int row = wm * 32 + mt * 16 + a_row;
                            int cu  = ks2 * 4 + ks * 2 + a_cuh;
                            uint32_t off = SWZ128((uint32_t)(row * 128 + cu * 16));
                            LDSM4(aF[mt], aB + off);
                        }
                        #pragma unroll
                        for (int mt = 0; mt < 2; mt++) {
                            MMAF16(accH[mt], aF[mt], bH[2 * ks], bH[2 * ks + 1]);
                            MMAF16(accL[mt], aF[mt], bL[2 * ks], bL[2 * ks + 1]);
                        }
                    }
                }
            }
            __syncthreads();
        }

        // ---- fused epilogue: shuffle gate-quad exchange + LSTM pointwise ----
        // Lane pair (lane^1) holds the other half of the gate quad:
        // even lane cols = gates f,i; odd lane cols = gates o,c~. Even handles
        // row r, odd handles row r+8 (both need all 4 gates via 4 shuffles).
        #pragma unroll
        for (int mt = 0; mt < 2; mt++) {
            float v0 = accH[mt][0] + accL[mt][0];
            float v1 = accH[mt][1] + accL[mt][1];
            float v2 = accH[mt][2] + accL[mt][2];
            float v3 = accH[mt][3] + accL[mt][3];
            float e0 = __shfl_xor_sync(0xffffffffu, v0, 1);
            float e1 = __shfl_xor_sync(0xffffffffu, v1, 1);
            float e2 = __shfl_xor_sync(0xffffffffu, v2, 1);
            float e3 = __shfl_xor_sync(0xffffffffu, v3, 1);
            float pf = (odd ? e2 : v0) + xpv[mt].x;
            float pi = (odd ? e3 : v1) + xpv[mt].y;
            float po = (odd ? v2 : e0) + xpv[mt].z;
            float pc = (odd ? v3 : e1) + xpv[mt].w;
            float fg = 1.f / (1.f + expf(-pf));
            float ig = 1.f / (1.f + expf(-pi));
            float og = 1.f / (1.f + expf(-po));
            float ct = tanhf(pc);
            cv[mt] = fg * cv[mt] + ig * ct;
            float hnew = og * tanhf(cv[mt]);
            __half hhi, hlo;
            split_f16(hnew, hhi, hlo);
            size_t ho = (size_t)t * BH + (size_t)eb[mt] * H_ + ju;
            g_Hshi[ho] = hhi;
            g_Hslo[ho] = hlo;
        }

        // ---- device-wide barrier: release step t ----
        __threadfence();
        __syncthreads();
        if (tid == 0) {
            unsigned old = atomicAdd(&g_bar_count, 1);
            if (old == (unsigned)(gridDim.x - 1)) {
                g_bar_count = 0;
                __threadfence();
                atomicExch(&g_bar_gen, (unsigned)(t + 1));
            } else {
                while (atomicAdd(&g_bar_gen, 0u) < (unsigned)(t + 1)) { }
            }
            __threadfence();
        }
        __syncthreads();
    }

    // write back cell state
    #pragma unroll
    for (int mt = 0; mt < 2; mt++)
        g_c[eb[mt] * H_ + ju] = cv[mt];
}

// ---------------- final h / c copy (hi+lo reconstruction) ----------------
__global__ void write_hc(float* __restrict__ dst)
{
    int i = blockIdx.x * blockDim.x + threadIdx.x;
    if (i < BH) {
        size_t o = (size_t)(T_ - 1) * BH + i;
        dst[i]      = __half2float(g_Hshi[o]) + __half2float(g_Hslo[o]);
        dst[BH + i] = g_c[i];
    }
}

// ---------------- launch ----------------
extern "C" void kernel_launch(void* const* d_in, const int* in_sizes, int n_in,
                              void* d_out, int out_size)
{
    const float* input_seq = (const float*)d_in[0];
    const float* hidden    = (const float*)d_in[1];
    const float* cell      = (const float*)d_in[2];
    const float* Wf        = (const float*)d_in[3];
    const float* bf        = (const float*)d_in[4];
    const float* Wi        = (const float*)d_in[5];
    const float* bi        = (const float*)d_in[6];
    const float* Wo        = (const float*)d_in[7];
    const float* bo        = (const float*)d_in[8];
    const float* Wc        = (const float*)d_in[9];
    const float* bc        = (const float*)d_in[10];
    const float* Wout      = (const float*)d_in[11];
    const float* bout      = (const float*)d_in[12];
    float* out = (float*)d_out;

    cudaFuncSetAttribute(gemm_f16_2t, cudaFuncAttributeMaxDynamicSharedMemorySize, GEMM_SMEM);
    cudaFuncSetAttribute(lstm_mma_persistent, cudaFuncAttributeMaxDynamicSharedMemorySize, REC_SMEM);

    float *pBias, *pX;
    __half *pXf, *pWxh, *pWxl, *pWoh, *pWol, *pHsh;
    cudaGetSymbolAddress((void**)&pBias, g_bias);
    cudaGetSymbolAddress((void**)&pX,    g_Xproj);
    cudaGetSymbolAddress((void**)&pXf,   g_Xf16);
    cudaGetSymbolAddress((void**)&pWxh,  g_WxThi);
    cudaGetSymbolAddress((void**)&pWxl,  g_WxTlo);
    cudaGetSymbolAddress((void**)&pWoh,  g_WoThi);
    cudaGetSymbolAddress((void**)&pWol,  g_WoTlo);
    cudaGetSymbolAddress((void**)&pHsh,  g_Hshi);

    // 1. packs + conversions
    pack_gates_t<<<48 * 32, 256>>>(Wf, Wi, Wo, Wc);
    pack_wout_t<<<32 * 8, 256>>>(Wout);
    {
        size_t n = (size_t)T_ * B_ * E_;
        convert_x<<<(int)((n + 255) / 256), 256>>>(input_seq, pXf, n);
    }
    init_state<<<(BH + 255) / 256, 256>>>(hidden, cell, bf, bi, bo, bc);

    // 2. Xproj = X @ WxT^T + bias  (M=32768, N=4096, K=512), fp16 2-term, 128x128
    {
        dim3 grid(G4 / 128, (T_ * B_) / 128);
        gemm_f16_2t<<<grid, 256, GEMM_SMEM>>>(pXf, pWxh, pWxl, pBias, pX, E_, G4);
    }

    // 3. recurrence (persistent tensor-core kernel, Wh smem-resident)
    lstm_mma_persistent<<<NCTA_STEP, 256, REC_SMEM>>>();

    // 4. out GEMM (M=32768, N=256, K=1024), fp16 2-term, 128x128
    {
        dim3 grid(V_ / 128, (T_ * B_) / 128);
        gemm_f16_2t<<<grid, 256, GEMM_SMEM>>>(pHsh, pWoh, pWol, bout, out, H_, V_);
    }

    // 5. final h, c
    write_hc<<<(BH + 255) / 256, 256>>>(out + (size_t)T_ * B_ * V_);
}